// round 5
// baseline (speedup 1.0000x reference)
#include <cuda_runtime.h>
#include <math.h>

namespace {

constexpr int CDIM = 512;
constexpr int MDIM = 512;
constexpr int TB   = 32;
constexpr int NT   = 512;

// smem: s_k[TB*C] | s_sc[TB*C] | s_keys[32*M] | s_inv[TB] | s_acc[3(+pad)]
constexpr int SMEM_FLOATS = TB * CDIM * 2 + 32 * MDIM + TB + 16;
constexpr int SMEM_BYTES  = SMEM_FLOATS * 4;

typedef unsigned long long u64;

__device__ __forceinline__ u64 splat2(float x) {
    u64 r; asm("mov.b64 %0, {%1, %1};" : "=l"(r) : "f"(x)); return r;
}
__device__ __forceinline__ void ffma2(u64& d, u64 a, u64 b) {
    asm("fma.rn.f32x2 %0, %1, %2, %0;" : "+l"(d) : "l"(a), "l"(b));
}
__device__ __forceinline__ float2 unpack2(u64 v) {
    float2 r; asm("mov.b64 {%0, %1}, %2;" : "=f"(r.x), "=f"(r.y) : "l"(v)); return r;
}

__global__ void zero_scalars_kernel(float* scalars) {
    if (threadIdx.x < 3) scalars[threadIdx.x] = 0.0f;
}

__global__ __launch_bounds__(NT, 1)
void memory_module_kernel(const float* __restrict__ key,
                          const float* __restrict__ query,
                          const float* __restrict__ keys,
                          const float* __restrict__ values,
                          float* __restrict__ out_read,
                          float* __restrict__ out_scalars) {
    extern __shared__ float smem[];
    float* s_k    = smem;                 // TB*CDIM (normalized k; later: values staging)
    float* s_sc   = smem + TB * CDIM;     // TB*CDIM (score -> exp(s-max))
    float* s_keys = s_sc + TB * CDIM;     // 32*MDIM (keys staging, layout [c][m])
    float* s_inv  = s_keys + 32 * MDIM;   // TB
    float* s_acc  = s_inv + TB;           // 3

    const int tid  = threadIdx.x;
    const int lane = tid & 31;
    const int warp = tid >> 5;            // 0..15
    const int tx4  = (tid & 63) * 4;      // 0..252, column group
    const int ty4  = (tid >> 6) * 4;      // row group
    const long long t0 = (long long)blockIdx.x * TB;

    if (tid < 3) s_acc[tid] = 0.0f;

    // ---------------- Phase A: L2-normalize key rows into s_k ----------------
    #pragma unroll
    for (int rr = 0; rr < 2; rr++) {
        const int r = warp * 2 + rr;
        const float4* kp = (const float4*)(key + (t0 + r) * CDIM);
        float4 v[4];
        float ss = 0.f;
        #pragma unroll
        for (int k2 = 0; k2 < 4; k2++) {
            v[k2] = kp[lane + 32 * k2];
            ss += v[k2].x * v[k2].x + v[k2].y * v[k2].y
                + v[k2].z * v[k2].z + v[k2].w * v[k2].w;
        }
        #pragma unroll
        for (int off = 16; off; off >>= 1) ss += __shfl_xor_sync(0xffffffffu, ss, off);
        const float inv = 1.0f / fmaxf(sqrtf(ss), 1e-12f);
        float4* dst = (float4*)(s_k + r * CDIM);
        #pragma unroll
        for (int k2 = 0; k2 < 4; k2++) {
            float4 o = v[k2];
            o.x *= inv; o.y *= inv; o.z *= inv; o.w *= inv;
            dst[lane + 32 * k2] = o;
        }
    }
    __syncthreads();

    // ---------------- Phase B: score[32][512] = k @ keys^T (f32x2) ----------------
    // Thread owns rows ty4..ty4+3, columns {tx4..tx4+3} and {256+tx4..256+tx4+3}.
    u64 acc[4][4];
    #pragma unroll
    for (int i = 0; i < 4; i++)
        #pragma unroll
        for (int j = 0; j < 4; j++) acc[i][j] = 0ull;

    for (int cs = 0; cs < CDIM; cs += 32) {
        // stage keys[:, cs..cs+31] transposed into s_keys[c][m] (conflict-free)
        for (int t = tid; t < 4096; t += NT) {
            const int m  = t & 511;
            const int c4 = (t >> 9) << 2;
            const float4 kv = *(const float4*)(keys + (size_t)m * CDIM + cs + c4);
            s_keys[(c4 + 0) * MDIM + m] = kv.x;
            s_keys[(c4 + 1) * MDIM + m] = kv.y;
            s_keys[(c4 + 2) * MDIM + m] = kv.z;
            s_keys[(c4 + 3) * MDIM + m] = kv.w;
        }
        __syncthreads();

        #pragma unroll 4
        for (int cc = 0; cc < 32; cc += 4) {
            float a_[4][4];
            #pragma unroll
            for (int i = 0; i < 4; i++) {
                const float4 av = *(const float4*)(s_k + (ty4 + i) * CDIM + cs + cc);
                a_[i][0] = av.x; a_[i][1] = av.y; a_[i][2] = av.z; a_[i][3] = av.w;
            }
            #pragma unroll
            for (int q = 0; q < 4; q++) {
                const float* bp = s_keys + (cc + q) * MDIM;
                const ulonglong2 b0 = *(const ulonglong2*)(bp + tx4);         // lanes contiguous
                const ulonglong2 b1 = *(const ulonglong2*)(bp + 256 + tx4);
                #pragma unroll
                for (int i = 0; i < 4; i++) {
                    const u64 pa = splat2(a_[i][q]);
                    ffma2(acc[i][0], pa, b0.x);
                    ffma2(acc[i][1], pa, b0.y);
                    ffma2(acc[i][2], pa, b1.x);
                    ffma2(acc[i][3], pa, b1.y);
                }
            }
        }
        __syncthreads();
    }
    // write score tile
    #pragma unroll
    for (int i = 0; i < 4; i++) {
        ulonglong2* d0 = (ulonglong2*)(s_sc + (ty4 + i) * CDIM + tx4);
        ulonglong2* d1 = (ulonglong2*)(s_sc + (ty4 + i) * CDIM + 256 + tx4);
        *d0 = make_ulonglong2(acc[i][0], acc[i][1]);
        *d1 = make_ulonglong2(acc[i][2], acc[i][3]);
    }
    __syncthreads();

    // ---------------- Phase C: per-row reductions ----------------
    {
        float ent = 0.f, con = 0.f, gat = 0.f;
        #pragma unroll
        for (int rr = 0; rr < 2; rr++) {
            const int r = warp * 2 + rr;
            float* srow = s_sc + r * CDIM;

            float mx = -1e30f; int mi = 0;
            #pragma unroll
            for (int k2 = 0; k2 < 16; k2++) {
                const float v = srow[lane + 32 * k2];
                if (v > mx) { mx = v; mi = lane + 32 * k2; }
            }
            #pragma unroll
            for (int off = 16; off; off >>= 1) {
                const float v2 = __shfl_down_sync(0xffffffffu, mx, off);
                const int   i2 = __shfl_down_sync(0xffffffffu, mi, off);
                if (v2 > mx || (v2 == mx && i2 < mi)) { mx = v2; mi = i2; }
            }
            mx = __shfl_sync(0xffffffffu, mx, 0);
            mi = __shfl_sync(0xffffffffu, mi, 0);

            float z1 = 0.f, z2 = 0.f, sw = 0.f;
            #pragma unroll
            for (int k2 = 0; k2 < 16; k2++) {
                const float s = srow[lane + 32 * k2];
                const float e = __expf(s - mx);
                z1 += e; z2 += e * e; sw += s * e;
                srow[lane + 32 * k2] = e;
            }
            #pragma unroll
            for (int off = 16; off; off >>= 1) {
                z1 += __shfl_xor_sync(0xffffffffu, z1, off);
                z2 += __shfl_xor_sync(0xffffffffu, z2, off);
                sw += __shfl_xor_sync(0xffffffffu, sw, off);
            }
            if (lane == 0) s_inv[r] = 1.0f / z1;

            const float4* qp = (const float4*)(query + (t0 + r) * CDIM);
            float4 qv[4];
            float ssq = 0.f;
            #pragma unroll
            for (int k2 = 0; k2 < 4; k2++) {
                qv[k2] = qp[lane + 32 * k2];
                ssq += qv[k2].x * qv[k2].x + qv[k2].y * qv[k2].y
                     + qv[k2].z * qv[k2].z + qv[k2].w * qv[k2].w;
            }
            #pragma unroll
            for (int off = 16; off; off >>= 1) ssq += __shfl_xor_sync(0xffffffffu, ssq, off);
            const float qi = 1.0f / fmaxf(sqrtf(ssq), 1e-12f);

            const float4* vp = (const float4*)(values + (size_t)mi * CDIM);
            float g = 0.f;
            #pragma unroll
            for (int k2 = 0; k2 < 4; k2++) {
                const float4 vv = vp[lane + 32 * k2];
                const float dx = qv[k2].x * qi - vv.x;
                const float dy = qv[k2].y * qi - vv.y;
                const float dz = qv[k2].z * qi - vv.z;
                const float dw = qv[k2].w * qi - vv.w;
                g += dx * dx + dy * dy + dz * dz + dw * dw;
            }
            #pragma unroll
            for (int off = 16; off; off >>= 1) g += __shfl_xor_sync(0xffffffffu, g, off);

            if (lane == 0) {
                ent += mx + logf(z1) - sw / z1;
                con += logf(z2);
                gat += g;
            }
        }
        if (lane == 0) {
            atomicAdd(&s_acc[0], ent);
            atomicAdd(&s_acc[1], gat);
            atomicAdd(&s_acc[2], con);
        }
    }
    __syncthreads();
    if (tid == 0) {
        atomicAdd(out_scalars + 0, s_acc[0] * (1.0f / 32768.0f));
        atomicAdd(out_scalars + 1, s_acc[1] * (1.0f / (32768.0f * 512.0f)));
        atomicAdd(out_scalars + 2, s_acc[2] * (1.0f / 12800.0f));
    }

    // ---------------- Phase D: read = softmax(score) @ values (f32x2) ----------------
    u64 racc[4][4];
    #pragma unroll
    for (int i = 0; i < 4; i++)
        #pragma unroll
        for (int j = 0; j < 4; j++) racc[i][j] = 0ull;

    for (int ms = 0; ms < MDIM; ms += 32) {
        const float4* vsrc = (const float4*)(values + (size_t)ms * CDIM);
        float4* vdst = (float4*)s_k;
        for (int t = tid; t < (32 * CDIM) / 4; t += NT) vdst[t] = vsrc[t];
        __syncthreads();

        #pragma unroll 4
        for (int mm = 0; mm < 32; mm += 4) {
            float w_[4][4];
            #pragma unroll
            for (int i = 0; i < 4; i++) {
                const float4 wv = *(const float4*)(s_sc + (ty4 + i) * CDIM + ms + mm);
                w_[i][0] = wv.x; w_[i][1] = wv.y; w_[i][2] = wv.z; w_[i][3] = wv.w;
            }
            #pragma unroll
            for (int q = 0; q < 4; q++) {
                const float* bp = s_k + (mm + q) * CDIM;
                const ulonglong2 b0 = *(const ulonglong2*)(bp + tx4);
                const ulonglong2 b1 = *(const ulonglong2*)(bp + 256 + tx4);
                #pragma unroll
                for (int i = 0; i < 4; i++) {
                    const u64 pw = splat2(w_[i][q]);
                    ffma2(racc[i][0], pw, b0.x);
                    ffma2(racc[i][1], pw, b0.y);
                    ffma2(racc[i][2], pw, b1.x);
                    ffma2(racc[i][3], pw, b1.y);
                }
            }
        }
        __syncthreads();
    }

    // epilogue: scale by 1/Z1, store
    #pragma unroll
    for (int i = 0; i < 4; i++) {
        const float sc = s_inv[ty4 + i];
        float* orow = out_read + (t0 + ty4 + i) * CDIM;
        const float2 p0 = unpack2(racc[i][0]);
        const float2 p1 = unpack2(racc[i][1]);
        const float2 p2 = unpack2(racc[i][2]);
        const float2 p3 = unpack2(racc[i][3]);
        *(float4*)(orow + tx4)       = make_float4(p0.x * sc, p0.y * sc, p1.x * sc, p1.y * sc);
        *(float4*)(orow + 256 + tx4) = make_float4(p2.x * sc, p2.y * sc, p3.x * sc, p3.y * sc);
    }
}

} // namespace

extern "C" void kernel_launch(void* const* d_in, const int* in_sizes, int n_in,
                              void* d_out, int out_size) {
    const float* key    = (const float*)d_in[0];
    const float* query  = (const float*)d_in[1];
    const float* keys   = (const float*)d_in[2];
    const float* values = (const float*)d_in[3];
    float* out = (float*)d_out;

    const size_t read_elems = (size_t)in_sizes[0];
    const size_t keys_elems = (size_t)in_sizes[2];
    const size_t vals_elems = (size_t)in_sizes[3];
    const long long T = (long long)(read_elems / CDIM);

    float* out_scalars = out + read_elems;
    float* out_keys    = out + read_elems + 3;
    float* out_values  = out_keys + keys_elems;

    cudaMemcpyAsync(out_keys,   keys,   keys_elems * sizeof(float), cudaMemcpyDeviceToDevice, 0);
    cudaMemcpyAsync(out_values, values, vals_elems * sizeof(float), cudaMemcpyDeviceToDevice, 0);

    zero_scalars_kernel<<<1, 32, 0, 0>>>(out_scalars);

    static bool attr_set = false;
    if (!attr_set) {
        cudaFuncSetAttribute(memory_module_kernel,
                             cudaFuncAttributeMaxDynamicSharedMemorySize, SMEM_BYTES);
        attr_set = true;
    }

    const int grid = (int)(T / TB);
    memory_module_kernel<<<grid, NT, SMEM_BYTES, 0>>>(key, query, keys, values,
                                                      out, out_scalars);
}

// round 9
// speedup vs baseline: 4.7565x; 4.7565x over previous
#include <cuda_runtime.h>
#include <cuda_bf16.h>
#include <cstdint>
#include <math.h>

namespace {

constexpr int CDIM = 512;
constexpr int MDIM = 512;
constexpr int ROWS = 64;     // rows per block
constexpr int NT   = 512;    // 16 warps

// SMEM byte offsets (dynamic)
constexpr int S_B   = 0;          // B chunk [512][72] bf16 = 73728
constexpr int S_W   = 73728;      // W tiles: 8 x [64][72] bf16 = 73728
constexpr int S_A   = 147456;     // A tile [64][72] bf16 = 9216
constexpr int S_P0  = 156672;     // [64][16] f32 partials
constexpr int S_P1  = 160768;
constexpr int S_P2  = 164864;
constexpr int S_PI  = 168960;     // [64][16] i32
constexpr int S_MX  = 173056;     // 64 f32
constexpr int S_MI  = 173312;     // 64 i32
constexpr int S_IZ  = 173568;     // 64 f32
constexpr int S_IN  = 173824;     // 64 f32
constexpr int S_ACC = 174080;     // 3 f32
constexpr int SMEM_BYTES = 174336;

__device__ __align__(16) __nv_bfloat16 g_keys_bf[MDIM * CDIM];  // [m][c]
__device__ __align__(16) __nv_bfloat16 g_vt_bf  [CDIM * MDIM];  // [c][m]

__device__ __forceinline__ uint32_t smem_u32(const void* p) {
    uint32_t a;
    asm("{ .reg .u64 t; cvta.to.shared.u64 t, %1; cvt.u32.u64 %0, t; }" : "=r"(a) : "l"(p));
    return a;
}
__device__ __forceinline__ unsigned pack_bf16(float lo, float hi) {
    unsigned r;
    asm("cvt.rn.bf16x2.f32 %0, %1, %2;" : "=r"(r) : "f"(hi), "f"(lo));
    return r;
}
__device__ __forceinline__ void ldm_x4(uint32_t& r0, uint32_t& r1, uint32_t& r2,
                                       uint32_t& r3, uint32_t addr) {
    asm volatile("ldmatrix.sync.aligned.m8n8.x4.shared.b16 {%0,%1,%2,%3}, [%4];"
                 : "=r"(r0), "=r"(r1), "=r"(r2), "=r"(r3) : "r"(addr));
}
__device__ __forceinline__ void ldm_x2(uint32_t& r0, uint32_t& r1, uint32_t addr) {
    asm volatile("ldmatrix.sync.aligned.m8n8.x2.shared.b16 {%0,%1}, [%2];"
                 : "=r"(r0), "=r"(r1) : "r"(addr));
}
__device__ __forceinline__ void hmma(float* d, uint32_t a0, uint32_t a1, uint32_t a2,
                                     uint32_t a3, uint32_t b0, uint32_t b1) {
    asm volatile("mma.sync.aligned.m16n8k16.row.col.f32.bf16.bf16.f32 "
                 "{%0,%1,%2,%3}, {%4,%5,%6,%7}, {%8,%9}, {%0,%1,%2,%3};"
                 : "+f"(d[0]), "+f"(d[1]), "+f"(d[2]), "+f"(d[3])
                 : "r"(a0), "r"(a1), "r"(a2), "r"(a3), "r"(b0), "r"(b1));
}

// ---- prep: keys -> bf16 [m][c] ----
__global__ void prep_keys_kernel(const float* __restrict__ keys) {
    const int m = blockIdx.x, t = threadIdx.x;  // 128 threads
    const float4 v = ((const float4*)(keys + (size_t)m * CDIM))[t];
    ((uint2*)(g_keys_bf + (size_t)m * CDIM))[t] =
        make_uint2(pack_bf16(v.x, v.y), pack_bf16(v.z, v.w));
}

// ---- prep: values^T -> bf16 [c][m] ----
__global__ void prep_vt_kernel(const float* __restrict__ values) {
    __shared__ float tile[64][65];
    const int m0 = blockIdx.x * 64, c0 = blockIdx.y * 64;
    const int t = threadIdx.x;  // 256
    #pragma unroll
    for (int i = 0; i < 4; i++) {
        const int idx = t + i * 256;
        const int ml = idx >> 4, cp = idx & 15;
        const float4 v = ((const float4*)(values + (size_t)(m0 + ml) * CDIM + c0))[cp];
        tile[ml][cp * 4 + 0] = v.x; tile[ml][cp * 4 + 1] = v.y;
        tile[ml][cp * 4 + 2] = v.z; tile[ml][cp * 4 + 3] = v.w;
    }
    __syncthreads();
    #pragma unroll
    for (int i = 0; i < 4; i++) {
        const int idx = t + i * 256;
        const int cl = idx >> 4, jp = (idx & 15) * 4;
        ((uint2*)(g_vt_bf + (size_t)(c0 + cl) * MDIM + m0))[idx & 15] =
            make_uint2(pack_bf16(tile[jp + 0][cl], tile[jp + 1][cl]),
                       pack_bf16(tile[jp + 2][cl], tile[jp + 3][cl]));
    }
}

__global__ void zero_scalars_kernel(float* scalars) {
    if (threadIdx.x < 3) scalars[threadIdx.x] = 0.0f;
}

__global__ __launch_bounds__(NT, 1)
void memory_module_kernel(const float* __restrict__ key,
                          const float* __restrict__ query,
                          const float* __restrict__ values,
                          float* __restrict__ out_read,
                          float* __restrict__ out_scalars) {
    extern __shared__ char sc[];
    const uint32_t sb = smem_u32(sc);
    const int tid = threadIdx.x;
    const int lane = tid & 31, w = tid >> 5;       // 16 warps
    const int g = lane >> 2, tg = lane & 3;
    const size_t t0 = (size_t)blockIdx.x * ROWS;

    float* s_p0 = (float*)(sc + S_P0);
    float* s_p1 = (float*)(sc + S_P1);
    float* s_p2 = (float*)(sc + S_P2);
    int*   s_pi = (int*)  (sc + S_PI);
    float* s_mx = (float*)(sc + S_MX);
    int*   s_mi = (int*)  (sc + S_MI);
    float* s_iz = (float*)(sc + S_IZ);
    float* s_in = (float*)(sc + S_IN);
    float* s_acc= (float*)(sc + S_ACC);

    if (tid < 3) s_acc[tid] = 0.f;

    // ---- key norms: warp w handles rows 4w..4w+3 ----
    #pragma unroll
    for (int rr = 0; rr < 4; rr++) {
        const int r = w * 4 + rr;
        const float4* kp = (const float4*)(key + (t0 + r) * CDIM);
        float ss = 0.f;
        #pragma unroll
        for (int i = 0; i < 4; i++) {
            const float4 v = kp[lane + 32 * i];
            ss += v.x * v.x + v.y * v.y + v.z * v.z + v.w * v.w;
        }
        #pragma unroll
        for (int off = 16; off; off >>= 1) ss += __shfl_xor_sync(0xffffffffu, ss, off);
        if (lane == 0) s_in[r] = 1.0f / fmaxf(sqrtf(ss), 1e-12f);
    }
    __syncthreads();

    float acc[4][4][4];
    #pragma unroll
    for (int mt = 0; mt < 4; mt++)
        #pragma unroll
        for (int nt = 0; nt < 4; nt++)
            #pragma unroll
            for (int e = 0; e < 4; e++) acc[mt][nt][e] = 0.f;

    // ---- GEMM1: score[64][512] = khat @ keys^T ----
    for (int kc = 0; kc < 8; kc++) {
        // stage A: khat chunk bf16 -> [64][72]
        {
            const int r = tid >> 3, j = tid & 7;
            const float4* sp = (const float4*)(key + (t0 + r) * CDIM + kc * 64 + j * 8);
            const float4 v0 = sp[0], v1 = sp[1];
            const float s = s_in[r];
            *(uint4*)(sc + S_A + r * 144 + j * 16) =
                make_uint4(pack_bf16(v0.x * s, v0.y * s), pack_bf16(v0.z * s, v0.w * s),
                           pack_bf16(v1.x * s, v1.y * s), pack_bf16(v1.z * s, v1.w * s));
        }
        // stage B: keys bf16 chunk -> [512][72]
        #pragma unroll
        for (int i = 0; i < 8; i++) {
            const int idx = tid + i * 512;
            const int m = idx >> 3, j = idx & 7;
            const uint4 v = *(const uint4*)(g_keys_bf + (size_t)m * CDIM + kc * 64 + j * 8);
            *(uint4*)(sc + S_B + m * 144 + j * 16) = v;
        }
        __syncthreads();
        #pragma unroll
        for (int ks = 0; ks < 4; ks++) {
            const int kb = ks * 16;
            uint32_t a[4][4];
            #pragma unroll
            for (int mt = 0; mt < 4; mt++)
                ldm_x4(a[mt][0], a[mt][1], a[mt][2], a[mt][3],
                       sb + S_A + (mt * 16 + (lane & 15)) * 144 + (kb + 8 * (lane >> 4)) * 2);
            #pragma unroll
            for (int nt = 0; nt < 4; nt++) {
                uint32_t b0, b1;
                ldm_x2(b0, b1,
                       sb + S_B + (w * 32 + nt * 8 + (lane & 7)) * 144 +
                       (kb + 8 * ((lane >> 3) & 1)) * 2);
                #pragma unroll
                for (int mt = 0; mt < 4; mt++)
                    hmma(acc[mt][nt], a[mt][0], a[mt][1], a[mt][2], a[mt][3], b0, b1);
            }
        }
        __syncthreads();
    }

    // ---- pass 1: per-row max / argmax (scores live in acc regs) ----
    #pragma unroll
    for (int mt = 0; mt < 4; mt++)
    #pragma unroll
    for (int h = 0; h < 2; h++) {
        const int row = mt * 16 + g + 8 * h;
        float v = -1e30f; int vi = 0;
        #pragma unroll
        for (int nt = 0; nt < 4; nt++)
        #pragma unroll
        for (int e = 0; e < 2; e++) {
            const float s = acc[mt][nt][2 * h + e];
            const int c = w * 32 + nt * 8 + tg * 2 + e;
            if (s > v) { v = s; vi = c; }
        }
        #pragma unroll
        for (int off = 1; off <= 2; off <<= 1) {
            const float v2 = __shfl_xor_sync(0xffffffffu, v, off);
            const int   i2 = __shfl_xor_sync(0xffffffffu, vi, off);
            if (v2 > v || (v2 == v && i2 < vi)) { v = v2; vi = i2; }
        }
        if (tg == 0) { s_p0[row * 16 + w] = v; s_pi[row * 16 + w] = vi; }
    }
    __syncthreads();
    if (tid < 64) {
        float v = -1e30f; int vi = 0;
        #pragma unroll
        for (int ww = 0; ww < 16; ww++) {
            const float v2 = s_p0[tid * 16 + ww];
            const int   i2 = s_pi[tid * 16 + ww];
            if (v2 > v || (v2 == v && i2 < vi)) { v = v2; vi = i2; }
        }
        s_mx[tid] = v; s_mi[tid] = vi;
    }
    __syncthreads();

    // ---- pass 2: exp, z1/z2/sw, write W bf16 tiles ----
    #pragma unroll
    for (int mt = 0; mt < 4; mt++)
    #pragma unroll
    for (int h = 0; h < 2; h++) {
        const int row = mt * 16 + g + 8 * h;
        const float mxr = s_mx[row];
        float z1 = 0.f, z2 = 0.f, swv = 0.f;
        #pragma unroll
        for (int nt = 0; nt < 4; nt++) {
            const float s0 = acc[mt][nt][2 * h + 0];
            const float s1 = acc[mt][nt][2 * h + 1];
            const float e0 = __expf(s0 - mxr);
            const float e1 = __expf(s1 - mxr);
            z1 += e0 + e1; z2 += e0 * e0 + e1 * e1; swv += s0 * e0 + s1 * e1;
            const int coff = (w & 1) * 32 + nt * 8 + tg * 2;
            *(uint32_t*)(sc + S_W + (w >> 1) * 9216 + row * 144 + coff * 2) =
                pack_bf16(e0, e1);
        }
        #pragma unroll
        for (int off = 1; off <= 2; off <<= 1) {
            z1  += __shfl_xor_sync(0xffffffffu, z1, off);
            z2  += __shfl_xor_sync(0xffffffffu, z2, off);
            swv += __shfl_xor_sync(0xffffffffu, swv, off);
        }
        if (tg == 0) {
            s_p0[row * 16 + w] = z1; s_p1[row * 16 + w] = z2; s_p2[row * 16 + w] = swv;
        }
    }
    __syncthreads();
    if (tid < 64) {
        float z1 = 0.f, z2 = 0.f, swv = 0.f;
        #pragma unroll
        for (int ww = 0; ww < 16; ww++) {
            z1 += s_p0[tid * 16 + ww]; z2 += s_p1[tid * 16 + ww]; swv += s_p2[tid * 16 + ww];
        }
        s_iz[tid] = 1.0f / z1;
        const float ent = s_mx[tid] + logf(z1) - swv / z1;
        const float con = logf(z2);
        atomicAdd(&s_acc[0], ent);
        atomicAdd(&s_acc[2], con);
    }

    // ---- gathering loss: warp w rows 4w..4w+3 (s_mi ready since pass1 sync) ----
    {
        float gat = 0.f;
        #pragma unroll
        for (int rr = 0; rr < 4; rr++) {
            const int r = w * 4 + rr;
            const int mir = s_mi[r];
            const float4* qp = (const float4*)(query + (t0 + r) * CDIM);
            float4 qv[4]; float ssq = 0.f;
            #pragma unroll
            for (int i = 0; i < 4; i++) {
                qv[i] = qp[lane + 32 * i];
                ssq += qv[i].x * qv[i].x + qv[i].y * qv[i].y
                     + qv[i].z * qv[i].z + qv[i].w * qv[i].w;
            }
            #pragma unroll
            for (int off = 16; off; off >>= 1) ssq += __shfl_xor_sync(0xffffffffu, ssq, off);
            const float qi = 1.0f / fmaxf(sqrtf(ssq), 1e-12f);
            const float4* vp = (const float4*)(values + (size_t)mir * CDIM);
            #pragma unroll
            for (int i = 0; i < 4; i++) {
                const float4 vv = vp[lane + 32 * i];
                const float dx = qv[i].x * qi - vv.x;
                const float dy = qv[i].y * qi - vv.y;
                const float dz = qv[i].z * qi - vv.z;
                const float dw = qv[i].w * qi - vv.w;
                gat += dx * dx + dy * dy + dz * dz + dw * dw;
            }
        }
        #pragma unroll
        for (int off = 16; off; off >>= 1) gat += __shfl_xor_sync(0xffffffffu, gat, off);
        if (lane == 0) atomicAdd(&s_acc[1], gat);
    }

    // ---- GEMM2: read[64][512] = W @ values ----
    #pragma unroll
    for (int mt = 0; mt < 4; mt++)
        #pragma unroll
        for (int nt = 0; nt < 4; nt++)
            #pragma unroll
            for (int e = 0; e < 4; e++) acc[mt][nt][e] = 0.f;

    for (int mc = 0; mc < 8; mc++) {
        #pragma unroll
        for (int i = 0; i < 8; i++) {
            const int idx = tid + i * 512;
            const int c = idx >> 3, j = idx & 7;
            const uint4 v = *(const uint4*)(g_vt_bf + (size_t)c * MDIM + mc * 64 + j * 8);
            *(uint4*)(sc + S_B + c * 144 + j * 16) = v;
        }
        __syncthreads();
        #pragma unroll
        for (int ks = 0; ks < 4; ks++) {
            const int kb = ks * 16;
            uint32_t a[4][4];
            #pragma unroll
            for (int mt = 0; mt < 4; mt++)
                ldm_x4(a[mt][0], a[mt][1], a[mt][2], a[mt][3],
                       sb + S_W + mc * 9216 + (mt * 16 + (lane & 15)) * 144 +
                       (kb + 8 * (lane >> 4)) * 2);
            #pragma unroll
            for (int nt = 0; nt < 4; nt++) {
                uint32_t b0, b1;
                ldm_x2(b0, b1,
                       sb + S_B + (w * 32 + nt * 8 + (lane & 7)) * 144 +
                       (kb + 8 * ((lane >> 3) & 1)) * 2);
                #pragma unroll
                for (int mt = 0; mt < 4; mt++)
                    hmma(acc[mt][nt], a[mt][0], a[mt][1], a[mt][2], a[mt][3], b0, b1);
            }
        }
        __syncthreads();
    }

    // ---- epilogue: scale by 1/z1, store ----
    #pragma unroll
    for (int mt = 0; mt < 4; mt++)
    #pragma unroll
    for (int h = 0; h < 2; h++) {
        const int row = mt * 16 + g + 8 * h;
        const float scl = s_iz[row];
        #pragma unroll
        for (int nt = 0; nt < 4; nt++) {
            const int c = w * 32 + nt * 8 + tg * 2;
            const float2 o = make_float2(acc[mt][nt][2 * h + 0] * scl,
                                         acc[mt][nt][2 * h + 1] * scl);
            *(float2*)(out_read + (t0 + row) * CDIM + c) = o;
        }
    }

    __syncthreads();
    if (tid == 0) {
        atomicAdd(out_scalars + 0, s_acc[0] * (1.0f / 32768.0f));
        atomicAdd(out_scalars + 1, s_acc[1] * (1.0f / (32768.0f * 512.0f)));
        atomicAdd(out_scalars + 2, s_acc[2] * (1.0f / 12800.0f));
    }
}

} // namespace

extern "C" void kernel_launch(void* const* d_in, const int* in_sizes, int n_in,
                              void* d_out, int out_size) {
    const float* key    = (const float*)d_in[0];
    const float* query  = (const float*)d_in[1];
    const float* keys   = (const float*)d_in[2];
    const float* values = (const float*)d_in[3];
    float* out = (float*)d_out;

    const size_t read_elems = (size_t)in_sizes[0];
    const size_t keys_elems = (size_t)in_sizes[2];
    const size_t vals_elems = (size_t)in_sizes[3];
    const long long T = (long long)(read_elems / CDIM);

    float* out_scalars = out + read_elems;
    float* out_keys    = out + read_elems + 3;
    float* out_values  = out_keys + keys_elems;

    cudaMemcpyAsync(out_keys,   keys,   keys_elems * sizeof(float), cudaMemcpyDeviceToDevice, 0);
    cudaMemcpyAsync(out_values, values, vals_elems * sizeof(float), cudaMemcpyDeviceToDevice, 0);

    zero_scalars_kernel<<<1, 32, 0, 0>>>(out_scalars);
    prep_keys_kernel<<<MDIM, 128, 0, 0>>>(keys);
    prep_vt_kernel<<<dim3(8, 8), 256, 0, 0>>>(values);

    static bool attr_set = false;
    if (!attr_set) {
        cudaFuncSetAttribute(memory_module_kernel,
                             cudaFuncAttributeMaxDynamicSharedMemorySize, SMEM_BYTES);
        attr_set = true;
    }

    const int grid = (int)(T / ROWS);   // 512
    memory_module_kernel<<<grid, NT, SMEM_BYTES, 0>>>(key, query, values,
                                                      out, out_scalars);
}

// round 10
// speedup vs baseline: 5.1738x; 1.0877x over previous
#include <cuda_runtime.h>
#include <cuda_bf16.h>
#include <cstdint>
#include <math.h>

namespace {

constexpr int CDIM = 512;
constexpr int MDIM = 512;
constexpr int ROWS = 64;     // rows per block
constexpr int NT   = 512;    // 16 warps

// SMEM byte offsets (dynamic)
constexpr int S_B0  = 0;          // B buffer 0: [512][128B] swizzled = 65536
constexpr int S_B1  = 65536;      // B buffer 1: 65536
constexpr int S_W   = 131072;     // W tiles: 8 x [64][144B] = 73728  -> 204800
constexpr int S_A0  = 204800;     // A buffer 0: [64][128B] swizzled = 8192
constexpr int S_A1  = 212992;     // A buffer 1: 8192 -> 221184
// partials overlaid on B1 (dead during reduction phase)
constexpr int S_P0  = 65536;      // [64][16] f32
constexpr int S_P1  = 69632;
constexpr int S_P2  = 73728;
constexpr int S_PI  = 77824;      // [64][16] i32
// persistent small arrays
constexpr int S_MX  = 221184;     // 64 f32
constexpr int S_MI  = 221440;     // 64 i32
constexpr int S_IZ  = 221696;     // 64 f32
constexpr int S_IN  = 221952;     // 64 f32
constexpr int S_ACC = 222208;     // 3 f32
constexpr int SMEM_BYTES = 222240;

__device__ __align__(16) __nv_bfloat16 g_keys_bf[MDIM * CDIM];  // [m][c]
__device__ __align__(16) __nv_bfloat16 g_vt_bf  [CDIM * MDIM];  // [c][m]

__device__ __forceinline__ uint32_t smem_u32(const void* p) {
    uint32_t a;
    asm("{ .reg .u64 t; cvta.to.shared.u64 t, %1; cvt.u32.u64 %0, t; }" : "=r"(a) : "l"(p));
    return a;
}
__device__ __forceinline__ unsigned pack_bf16(float lo, float hi) {
    unsigned r;
    asm("cvt.rn.bf16x2.f32 %0, %1, %2;" : "=r"(r) : "f"(hi), "f"(lo));
    return r;
}
__device__ __forceinline__ void ldm_x4(uint32_t& r0, uint32_t& r1, uint32_t& r2,
                                       uint32_t& r3, uint32_t addr) {
    asm volatile("ldmatrix.sync.aligned.m8n8.x4.shared.b16 {%0,%1,%2,%3}, [%4];"
                 : "=r"(r0), "=r"(r1), "=r"(r2), "=r"(r3) : "r"(addr));
}
__device__ __forceinline__ void ldm_x2(uint32_t& r0, uint32_t& r1, uint32_t addr) {
    asm volatile("ldmatrix.sync.aligned.m8n8.x2.shared.b16 {%0,%1}, [%2];"
                 : "=r"(r0), "=r"(r1) : "r"(addr));
}
__device__ __forceinline__ void hmma(float* d, uint32_t a0, uint32_t a1, uint32_t a2,
                                     uint32_t a3, uint32_t b0, uint32_t b1) {
    asm volatile("mma.sync.aligned.m16n8k16.row.col.f32.bf16.bf16.f32 "
                 "{%0,%1,%2,%3}, {%4,%5,%6,%7}, {%8,%9}, {%0,%1,%2,%3};"
                 : "+f"(d[0]), "+f"(d[1]), "+f"(d[2]), "+f"(d[3])
                 : "r"(a0), "r"(a1), "r"(a2), "r"(a3), "r"(b0), "r"(b1));
}
#define CP_COMMIT() asm volatile("cp.async.commit_group;" ::: "memory")
#define CP_WAIT0()  asm volatile("cp.async.wait_group 0;" ::: "memory")

// async-stage one 512x64bf16 chunk (64KB) into swizzled [row][seg^row&7] layout
__device__ __forceinline__ void stage_b_async(uint32_t dst_base_u32,
                                              const __nv_bfloat16* gbase,
                                              int chunk, int tid) {
    const char* g = (const char*)gbase + chunk * 128;
    #pragma unroll
    for (int i = 0; i < 8; i++) {
        const int idx = tid + i * 512;
        const int m = idx >> 3, j = idx & 7;
        asm volatile("cp.async.cg.shared.global [%0], [%1], 16;"
                     :: "r"(dst_base_u32 + m * 128 + (((j ^ (m & 7)) << 4))),
                        "l"(g + (size_t)m * 1024 + j * 16) : "memory");
    }
}

// ---- prep: keys -> bf16 [m][c] ----
__global__ void prep_keys_kernel(const float* __restrict__ keys) {
    const int m = blockIdx.x, t = threadIdx.x;  // 128 threads
    const float4 v = ((const float4*)(keys + (size_t)m * CDIM))[t];
    ((uint2*)(g_keys_bf + (size_t)m * CDIM))[t] =
        make_uint2(pack_bf16(v.x, v.y), pack_bf16(v.z, v.w));
}

// ---- prep: values^T -> bf16 [c][m] ----
__global__ void prep_vt_kernel(const float* __restrict__ values) {
    __shared__ float tile[64][65];
    const int m0 = blockIdx.x * 64, c0 = blockIdx.y * 64;
    const int t = threadIdx.x;  // 256
    #pragma unroll
    for (int i = 0; i < 4; i++) {
        const int idx = t + i * 256;
        const int ml = idx >> 4, cp = idx & 15;
        const float4 v = ((const float4*)(values + (size_t)(m0 + ml) * CDIM + c0))[cp];
        tile[ml][cp * 4 + 0] = v.x; tile[ml][cp * 4 + 1] = v.y;
        tile[ml][cp * 4 + 2] = v.z; tile[ml][cp * 4 + 3] = v.w;
    }
    __syncthreads();
    #pragma unroll
    for (int i = 0; i < 4; i++) {
        const int idx = t + i * 256;
        const int cl = idx >> 4, jp = (idx & 15) * 4;
        ((uint2*)(g_vt_bf + (size_t)(c0 + cl) * MDIM + m0))[idx & 15] =
            make_uint2(pack_bf16(tile[jp + 0][cl], tile[jp + 1][cl]),
                       pack_bf16(tile[jp + 2][cl], tile[jp + 3][cl]));
    }
}

__global__ void zero_scalars_kernel(float* scalars) {
    if (threadIdx.x < 3) scalars[threadIdx.x] = 0.0f;
}

__global__ __launch_bounds__(NT, 1)
void memory_module_kernel(const float* __restrict__ key,
                          const float* __restrict__ query,
                          const float* __restrict__ values,
                          float* __restrict__ out_read,
                          float* __restrict__ out_scalars) {
    extern __shared__ char sc[];
    const uint32_t sb = smem_u32(sc);
    const int tid = threadIdx.x;
    const int lane = tid & 31, w = tid >> 5;       // 16 warps
    const int g = lane >> 2, tg = lane & 3;
    const size_t t0 = (size_t)blockIdx.x * ROWS;

    float* s_p0 = (float*)(sc + S_P0);
    float* s_p1 = (float*)(sc + S_P1);
    float* s_p2 = (float*)(sc + S_P2);
    int*   s_pi = (int*)  (sc + S_PI);
    float* s_mx = (float*)(sc + S_MX);
    int*   s_mi = (int*)  (sc + S_MI);
    float* s_iz = (float*)(sc + S_IZ);
    float* s_in = (float*)(sc + S_IN);
    float* s_acc= (float*)(sc + S_ACC);

    if (tid < 3) s_acc[tid] = 0.f;

    // prefetch GEMM1 chunk 0 B tile (overlaps norm phase)
    stage_b_async(sb + S_B0, g_keys_bf, 0, tid);
    CP_COMMIT();

    // A register prefetch for chunk 0
    const int ar = tid >> 3, aj = tid & 7;
    float4 av0, av1;
    {
        const float4* ap = (const float4*)(key + (t0 + ar) * CDIM + aj * 8);
        av0 = ap[0]; av1 = ap[1];
    }

    // ---- key norms: warp w handles rows 4w..4w+3 ----
    #pragma unroll
    for (int rr = 0; rr < 4; rr++) {
        const int r = w * 4 + rr;
        const float4* kp = (const float4*)(key + (t0 + r) * CDIM);
        float ss = 0.f;
        #pragma unroll
        for (int i = 0; i < 4; i++) {
            const float4 v = kp[lane + 32 * i];
            ss += v.x * v.x + v.y * v.y + v.z * v.z + v.w * v.w;
        }
        #pragma unroll
        for (int off = 16; off; off >>= 1) ss += __shfl_xor_sync(0xffffffffu, ss, off);
        if (lane == 0) s_in[r] = 1.0f / fmaxf(sqrtf(ss), 1e-12f);
    }
    __syncthreads();

    float acc[4][4][4];
    #pragma unroll
    for (int mt = 0; mt < 4; mt++)
        #pragma unroll
        for (int nt = 0; nt < 4; nt++)
            #pragma unroll
            for (int e = 0; e < 4; e++) acc[mt][nt][e] = 0.f;

    // ---- GEMM1: score[64][512] = khat @ keys^T (pipelined) ----
    for (int kc = 0; kc < 8; kc++) {
        // stage A[kc&1] from prefetched regs (swizzled 128B rows)
        {
            const float s = s_in[ar];
            *(uint4*)(sc + S_A0 + (kc & 1) * 8192 + ar * 128 + (((aj ^ (ar & 7)) << 4))) =
                make_uint4(pack_bf16(av0.x * s, av0.y * s), pack_bf16(av0.z * s, av0.w * s),
                           pack_bf16(av1.x * s, av1.y * s), pack_bf16(av1.z * s, av1.w * s));
        }
        if (kc < 7) {
            const float4* ap = (const float4*)(key + (t0 + ar) * CDIM + (kc + 1) * 64 + aj * 8);
            av0 = ap[0]; av1 = ap[1];
        }
        CP_WAIT0();
        __syncthreads();   // B chunk kc arrived + A tile kc visible + prev MMA done
        if (kc < 7) {      // prefetch B chunk kc+1 into other buffer (overlaps MMA kc)
            stage_b_async(sb + S_B0 + ((kc + 1) & 1) * 65536, g_keys_bf, kc + 1, tid);
            CP_COMMIT();
        }
        const uint32_t abase = sb + S_A0 + (kc & 1) * 8192;
        const uint32_t bbase = sb + S_B0 + (kc & 1) * 65536;
        #pragma unroll
        for (int ks = 0; ks < 4; ks++) {
            uint32_t a[4][4];
            #pragma unroll
            for (int mt = 0; mt < 4; mt++) {
                const int row = mt * 16 + (lane & 15);
                const int seg = ks * 2 + (lane >> 4);
                ldm_x4(a[mt][0], a[mt][1], a[mt][2], a[mt][3],
                       abase + row * 128 + (((seg ^ (row & 7)) << 4)));
            }
            #pragma unroll
            for (int nt = 0; nt < 4; nt++) {
                const int row = w * 32 + nt * 8 + (lane & 7);
                const int seg = ks * 2 + ((lane >> 3) & 1);
                uint32_t b0, b1;
                ldm_x2(b0, b1, bbase + row * 128 + (((seg ^ (row & 7)) << 4)));
                #pragma unroll
                for (int mt = 0; mt < 4; mt++)
                    hmma(acc[mt][nt], a[mt][0], a[mt][1], a[mt][2], a[mt][3], b0, b1);
            }
        }
    }

    // prefetch GEMM2 chunk 0 (vt) into B0 — overlaps entire loss phase.
    // Safe: B0 last read at MMA chunk 6, complete before chunk-7 barrier.
    stage_b_async(sb + S_B0, g_vt_bf, 0, tid);
    CP_COMMIT();
    __syncthreads();   // all MMA(7) reads of B1 done before partials overlay B1

    // ---- pass 1: per-row max / argmax ----
    #pragma unroll
    for (int mt = 0; mt < 4; mt++)
    #pragma unroll
    for (int h = 0; h < 2; h++) {
        const int row = mt * 16 + g + 8 * h;
        float v = -1e30f; int vi = 0;
        #pragma unroll
        for (int nt = 0; nt < 4; nt++)
        #pragma unroll
        for (int e = 0; e < 2; e++) {
            const float s = acc[mt][nt][2 * h + e];
            const int c = w * 32 + nt * 8 + tg * 2 + e;
            if (s > v) { v = s; vi = c; }
        }
        #pragma unroll
        for (int off = 1; off <= 2; off <<= 1) {
            const float v2 = __shfl_xor_sync(0xffffffffu, v, off);
            const int   i2 = __shfl_xor_sync(0xffffffffu, vi, off);
            if (v2 > v || (v2 == v && i2 < vi)) { v = v2; vi = i2; }
        }
        if (tg == 0) { s_p0[row * 16 + w] = v; s_pi[row * 16 + w] = vi; }
    }
    __syncthreads();
    if (tid < 64) {
        float v = -1e30f; int vi = 0;
        #pragma unroll
        for (int ww = 0; ww < 16; ww++) {
            const float v2 = s_p0[tid * 16 + ww];
            const int   i2 = s_pi[tid * 16 + ww];
            if (v2 > v || (v2 == v && i2 < vi)) { v = v2; vi = i2; }
        }
        s_mx[tid] = v; s_mi[tid] = vi;
    }
    __syncthreads();

    // ---- pass 2: exp, z1/z2/sw, write W bf16 tiles ----
    #pragma unroll
    for (int mt = 0; mt < 4; mt++)
    #pragma unroll
    for (int h = 0; h < 2; h++) {
        const int row = mt * 16 + g + 8 * h;
        const float mxr = s_mx[row];
        float z1 = 0.f, z2 = 0.f, swv = 0.f;
        #pragma unroll
        for (int nt = 0; nt < 4; nt++) {
            const float s0 = acc[mt][nt][2 * h + 0];
            const float s1 = acc[mt][nt][2 * h + 1];
            const float e0 = __expf(s0 - mxr);
            const float e1 = __expf(s1 - mxr);
            z1 += e0 + e1; z2 += e0 * e0 + e1 * e1; swv += s0 * e0 + s1 * e1;
            const int coff = (w & 1) * 32 + nt * 8 + tg * 2;
            *(uint32_t*)(sc + S_W + (w >> 1) * 9216 + row * 144 + coff * 2) =
                pack_bf16(e0, e1);
        }
        #pragma unroll
        for (int off = 1; off <= 2; off <<= 1) {
            z1  += __shfl_xor_sync(0xffffffffu, z1, off);
            z2  += __shfl_xor_sync(0xffffffffu, z2, off);
            swv += __shfl_xor_sync(0xffffffffu, swv, off);
        }
        if (tg == 0) {
            s_p0[row * 16 + w] = z1; s_p1[row * 16 + w] = z2; s_p2[row * 16 + w] = swv;
        }
    }
    __syncthreads();
    if (tid < 64) {
        float z1 = 0.f, z2 = 0.f, swv = 0.f;
        #pragma unroll
        for (int ww = 0; ww < 16; ww++) {
            z1 += s_p0[tid * 16 + ww]; z2 += s_p1[tid * 16 + ww]; swv += s_p2[tid * 16 + ww];
        }
        s_iz[tid] = 1.0f / z1;
        const float ent = s_mx[tid] + logf(z1) - swv / z1;
        const float con = logf(z2);
        atomicAdd(&s_acc[0], ent);
        atomicAdd(&s_acc[2], con);
    }

    // ---- gathering loss: warp w rows 4w..4w+3 ----
    {
        float gat = 0.f;
        #pragma unroll
        for (int rr = 0; rr < 4; rr++) {
            const int r = w * 4 + rr;
            const int mir = s_mi[r];
            const float4* qp = (const float4*)(query + (t0 + r) * CDIM);
            float4 qv[4]; float ssq = 0.f;
            #pragma unroll
            for (int i = 0; i < 4; i++) {
                qv[i] = qp[lane + 32 * i];
                ssq += qv[i].x * qv[i].x + qv[i].y * qv[i].y
                     + qv[i].z * qv[i].z + qv[i].w * qv[i].w;
            }
            #pragma unroll
            for (int off = 16; off; off >>= 1) ssq += __shfl_xor_sync(0xffffffffu, ssq, off);
            const float qi = 1.0f / fmaxf(sqrtf(ssq), 1e-12f);
            const float4* vp = (const float4*)(values + (size_t)mir * CDIM);
            #pragma unroll
            for (int i = 0; i < 4; i++) {
                const float4 vv = vp[lane + 32 * i];
                const float dx = qv[i].x * qi - vv.x;
                const float dy = qv[i].y * qi - vv.y;
                const float dz = qv[i].z * qi - vv.z;
                const float dw = qv[i].w * qi - vv.w;
                gat += dx * dx + dy * dy + dz * dz + dw * dw;
            }
        }
        #pragma unroll
        for (int off = 16; off; off >>= 1) gat += __shfl_xor_sync(0xffffffffu, gat, off);
        if (lane == 0) atomicAdd(&s_acc[1], gat);
    }

    // ---- GEMM2: read[64][512] = W @ values (pipelined) ----
    #pragma unroll
    for (int mt = 0; mt < 4; mt++)
        #pragma unroll
        for (int nt = 0; nt < 4; nt++)
            #pragma unroll
            for (int e = 0; e < 4; e++) acc[mt][nt][e] = 0.f;

    for (int mc = 0; mc < 8; mc++) {
        CP_WAIT0();
        __syncthreads();   // B chunk mc arrived; P-array reads done (mc==0); prev MMA done
        if (mc < 7) {
            stage_b_async(sb + S_B0 + ((mc + 1) & 1) * 65536, g_vt_bf, mc + 1, tid);
            CP_COMMIT();
        }
        const uint32_t wbase = sb + S_W + mc * 9216;
        const uint32_t bbase = sb + S_B0 + (mc & 1) * 65536;
        #pragma unroll
        for (int ks = 0; ks < 4; ks++) {
            uint32_t a[4][4];
            #pragma unroll
            for (int mt = 0; mt < 4; mt++)
                ldm_x4(a[mt][0], a[mt][1], a[mt][2], a[mt][3],
                       wbase + (mt * 16 + (lane & 15)) * 144 + (ks * 16 + 8 * (lane >> 4)) * 2);
            #pragma unroll
            for (int nt = 0; nt < 4; nt++) {
                const int row = w * 32 + nt * 8 + (lane & 7);
                const int seg = ks * 2 + ((lane >> 3) & 1);
                uint32_t b0, b1;
                ldm_x2(b0, b1, bbase + row * 128 + (((seg ^ (row & 7)) << 4)));
                #pragma unroll
                for (int mt = 0; mt < 4; mt++)
                    hmma(acc[mt][nt], a[mt][0], a[mt][1], a[mt][2], a[mt][3], b0, b1);
            }
        }
    }

    // ---- epilogue: scale by 1/z1, store ----
    #pragma unroll
    for (int mt = 0; mt < 4; mt++)
    #pragma unroll
    for (int h = 0; h < 2; h++) {
        const int row = mt * 16 + g + 8 * h;
        const float scl = s_iz[row];
        #pragma unroll
        for (int nt = 0; nt < 4; nt++) {
            const int c = w * 32 + nt * 8 + tg * 2;
            const float2 o = make_float2(acc[mt][nt][2 * h + 0] * scl,
                                         acc[mt][nt][2 * h + 1] * scl);
            *(float2*)(out_read + (t0 + row) * CDIM + c) = o;
        }
    }

    __syncthreads();
    if (tid == 0) {
        atomicAdd(out_scalars + 0, s_acc[0] * (1.0f / 32768.0f));
        atomicAdd(out_scalars + 1, s_acc[1] * (1.0f / (32768.0f * 512.0f)));
        atomicAdd(out_scalars + 2, s_acc[2] * (1.0f / 12800.0f));
    }
}

} // namespace

extern "C" void kernel_launch(void* const* d_in, const int* in_sizes, int n_in,
                              void* d_out, int out_size) {
    const float* key    = (const float*)d_in[0];
    const float* query  = (const float*)d_in[1];
    const float* keys   = (const float*)d_in[2];
    const float* values = (const float*)d_in[3];
    float* out = (float*)d_out;

    const size_t read_elems = (size_t)in_sizes[0];
    const size_t keys_elems = (size_t)in_sizes[2];
    const size_t vals_elems = (size_t)in_sizes[3];
    const long long T = (long long)(read_elems / CDIM);

    float* out_scalars = out + read_elems;
    float* out_keys    = out + read_elems + 3;
    float* out_values  = out_keys + keys_elems;

    cudaMemcpyAsync(out_keys,   keys,   keys_elems * sizeof(float), cudaMemcpyDeviceToDevice, 0);
    cudaMemcpyAsync(out_values, values, vals_elems * sizeof(float), cudaMemcpyDeviceToDevice, 0);

    zero_scalars_kernel<<<1, 32, 0, 0>>>(out_scalars);
    prep_keys_kernel<<<MDIM, 128, 0, 0>>>(keys);
    prep_vt_kernel<<<dim3(8, 8), 256, 0, 0>>>(values);

    static bool attr_set = false;
    if (!attr_set) {
        cudaFuncSetAttribute(memory_module_kernel,
                             cudaFuncAttributeMaxDynamicSharedMemorySize, SMEM_BYTES);
        attr_set = true;
    }

    const int grid = (int)(T / ROWS);   // 512
    memory_module_kernel<<<grid, NT, SMEM_BYTES, 0>>>(key, query, values,
                                                      out, out_scalars);
}

// round 13
// speedup vs baseline: 5.6238x; 1.0870x over previous
#include <cuda_runtime.h>
#include <cuda_bf16.h>
#include <cstdint>
#include <math.h>

namespace {

constexpr int CDIM = 512;
constexpr int MDIM = 512;
constexpr int ROWS = 64;     // rows per block
constexpr int NT   = 512;    // 16 warps

// SMEM byte offsets (dynamic)
constexpr int S_B0  = 0;          // B buffer 0: [512][128B] swizzled = 65536
constexpr int S_B1  = 65536;      // B buffer 1: 65536
constexpr int S_W   = 131072;     // A_all during GEMM1, W tiles after pass2:
                                  // 8 chunks x [64][128B] swizzled = 65536
// partials overlaid on B1 (dead during reduction phase)
constexpr int S_P0  = 65536;      // [64][16] f32
constexpr int S_P1  = 69632;
constexpr int S_P2  = 73728;
constexpr int S_PI  = 77824;      // [64][16] i32
// persistent small arrays
constexpr int S_MX  = 196608;     // 64 f32
constexpr int S_MI  = 196864;     // 64 i32
constexpr int S_IZ  = 197120;     // 64 f32
constexpr int S_ACC = 197376;     // 3 f32
constexpr int SMEM_BYTES = 197408;

__device__ __align__(16) __nv_bfloat16 g_keys_bf[MDIM * CDIM];  // [m][c]
__device__ __align__(16) __nv_bfloat16 g_vt_bf  [CDIM * MDIM];  // [c][m]

__device__ __forceinline__ uint32_t smem_u32(const void* p) {
    uint32_t a;
    asm("{ .reg .u64 t; cvta.to.shared.u64 t, %1; cvt.u32.u64 %0, t; }" : "=r"(a) : "l"(p));
    return a;
}
__device__ __forceinline__ unsigned pack_bf16(float lo, float hi) {
    unsigned r;
    asm("cvt.rn.bf16x2.f32 %0, %1, %2;" : "=r"(r) : "f"(hi), "f"(lo));
    return r;
}
__device__ __forceinline__ void ldm_x4(uint32_t& r0, uint32_t& r1, uint32_t& r2,
                                       uint32_t& r3, uint32_t addr) {
    asm volatile("ldmatrix.sync.aligned.m8n8.x4.shared.b16 {%0,%1,%2,%3}, [%4];"
                 : "=r"(r0), "=r"(r1), "=r"(r2), "=r"(r3) : "r"(addr));
}
__device__ __forceinline__ void hmma(float* d, uint32_t a0, uint32_t a1, uint32_t a2,
                                     uint32_t a3, uint32_t b0, uint32_t b1) {
    asm volatile("mma.sync.aligned.m16n8k16.row.col.f32.bf16.bf16.f32 "
                 "{%0,%1,%2,%3}, {%4,%5,%6,%7}, {%8,%9}, {%0,%1,%2,%3};"
                 : "+f"(d[0]), "+f"(d[1]), "+f"(d[2]), "+f"(d[3])
                 : "r"(a0), "r"(a1), "r"(a2), "r"(a3), "r"(b0), "r"(b1));
}
#define CP_COMMIT() asm volatile("cp.async.commit_group;" ::: "memory")
#define CP_WAIT0()  asm volatile("cp.async.wait_group 0;" ::: "memory")

// async-stage one 512x64bf16 chunk (64KB) into swizzled [row][seg^row&7] layout
__device__ __forceinline__ void stage_b_async(uint32_t dst_base_u32,
                                              const __nv_bfloat16* gbase,
                                              int chunk, int tid) {
    const char* g = (const char*)gbase + chunk * 128;
    #pragma unroll
    for (int i = 0; i < 8; i++) {
        const int idx = tid + i * 512;
        const int m = idx >> 3, j = idx & 7;
        asm volatile("cp.async.cg.shared.global [%0], [%1], 16;"
                     :: "r"(dst_base_u32 + m * 128 + (((j ^ (m & 7)) << 4))),
                        "l"(g + (size_t)m * 1024 + j * 16) : "memory");
    }
}

// ---- prep: keys -> bf16 [m][c] ----
__global__ void prep_keys_kernel(const float* __restrict__ keys) {
    const int m = blockIdx.x, t = threadIdx.x;  // 128 threads
    const float4 v = ((const float4*)(keys + (size_t)m * CDIM))[t];
    ((uint2*)(g_keys_bf + (size_t)m * CDIM))[t] =
        make_uint2(pack_bf16(v.x, v.y), pack_bf16(v.z, v.w));
}

// ---- prep: values^T -> bf16 [c][m] ----
__global__ void prep_vt_kernel(const float* __restrict__ values) {
    __shared__ float tile[64][65];
    const int m0 = blockIdx.x * 64, c0 = blockIdx.y * 64;
    const int t = threadIdx.x;  // 256
    #pragma unroll
    for (int i = 0; i < 4; i++) {
        const int idx = t + i * 256;
        const int ml = idx >> 4, cp = idx & 15;
        const float4 v = ((const float4*)(values + (size_t)(m0 + ml) * CDIM + c0))[cp];
        tile[ml][cp * 4 + 0] = v.x; tile[ml][cp * 4 + 1] = v.y;
        tile[ml][cp * 4 + 2] = v.z; tile[ml][cp * 4 + 3] = v.w;
    }
    __syncthreads();
    #pragma unroll
    for (int i = 0; i < 4; i++) {
        const int idx = t + i * 256;
        const int cl = idx >> 4, jp = (idx & 15) * 4;
        ((uint2*)(g_vt_bf + (size_t)(c0 + cl) * MDIM + m0))[idx & 15] =
            make_uint2(pack_bf16(tile[jp + 0][cl], tile[jp + 1][cl]),
                       pack_bf16(tile[jp + 2][cl], tile[jp + 3][cl]));
    }
}

__global__ void zero_scalars_kernel(float* scalars) {
    if (threadIdx.x < 3) scalars[threadIdx.x] = 0.0f;
}

__global__ __launch_bounds__(NT, 1)
void memory_module_kernel(const float* __restrict__ key,
                          const float* __restrict__ query,
                          const float* __restrict__ values,
                          float* __restrict__ out_read,
                          float* __restrict__ out_scalars) {
    extern __shared__ char sc[];
    const uint32_t sb = smem_u32(sc);
    const int tid = threadIdx.x;
    const int lane = tid & 31, w = tid >> 5;       // 16 warps
    const int g = lane >> 2, tg = lane & 3;
    const size_t t0 = (size_t)blockIdx.x * ROWS;

    float* s_p0 = (float*)(sc + S_P0);
    float* s_p1 = (float*)(sc + S_P1);
    float* s_p2 = (float*)(sc + S_P2);
    int*   s_pi = (int*)  (sc + S_PI);
    float* s_mx = (float*)(sc + S_MX);
    int*   s_mi = (int*)  (sc + S_MI);
    float* s_iz = (float*)(sc + S_IZ);
    float* s_acc= (float*)(sc + S_ACC);

    if (tid < 3) s_acc[tid] = 0.f;

    // prefetch GEMM1 chunk 0 B tile (overlaps norm phase)
    stage_b_async(sb + S_B0, g_keys_bf, 0, tid);
    CP_COMMIT();

    // ---- norm phase: normalize key rows, write bf16 A_all (chunked swizzled) ----
    #pragma unroll
    for (int rr = 0; rr < 4; rr++) {
        const int r = w * 4 + rr;
        const float4* kp = (const float4*)(key + (t0 + r) * CDIM);
        float4 v[4];
        float ss = 0.f;
        #pragma unroll
        for (int i = 0; i < 4; i++) {
            v[i] = kp[lane + 32 * i];
            ss += v[i].x * v[i].x + v[i].y * v[i].y + v[i].z * v[i].z + v[i].w * v[i].w;
        }
        #pragma unroll
        for (int off = 16; off; off >>= 1) ss += __shfl_xor_sync(0xffffffffu, ss, off);
        const float inv = 1.0f / fmaxf(sqrtf(ss), 1e-12f);
        #pragma unroll
        for (int i = 0; i < 4; i++) {
            const int c0 = (lane + 32 * i) * 4;     // multiple of 4
            const int cin = c0 & 63;
            *(uint2*)(sc + S_W + (c0 >> 6) * 8192 + r * 128 +
                      ((((cin >> 3) ^ (r & 7)) << 4)) + ((cin & 7) * 2)) =
                make_uint2(pack_bf16(v[i].x * inv, v[i].y * inv),
                           pack_bf16(v[i].z * inv, v[i].w * inv));
        }
    }
    __syncthreads();

    float acc[4][4][4];
    #pragma unroll
    for (int mt = 0; mt < 4; mt++)
        #pragma unroll
        for (int nt = 0; nt < 4; nt++)
            #pragma unroll
            for (int e = 0; e < 4; e++) acc[mt][nt][e] = 0.f;

    // ---- GEMM1: score[64][512] = khat @ keys^T (A resident, B pipelined) ----
    for (int kc = 0; kc < 8; kc++) {
        CP_WAIT0();
        __syncthreads();   // B chunk kc arrived; prev MMA done
        if (kc < 7) {
            stage_b_async(sb + S_B0 + ((kc + 1) & 1) * 65536, g_keys_bf, kc + 1, tid);
            CP_COMMIT();
        }
        const uint32_t abase = sb + S_W + kc * 8192;
        const uint32_t bbase = sb + S_B0 + (kc & 1) * 65536;
        #pragma unroll
        for (int ks = 0; ks < 4; ks++) {
            uint32_t a[4][4];
            #pragma unroll
            for (int mt = 0; mt < 4; mt++) {
                const int row = mt * 16 + (lane & 15);
                const int seg = ks * 2 + (lane >> 4);
                ldm_x4(a[mt][0], a[mt][1], a[mt][2], a[mt][3],
                       abase + row * 128 + (((seg ^ (row & 7)) << 4)));
            }
            uint32_t b[2][4];
            #pragma unroll
            for (int p = 0; p < 2; p++) {
                const int row = w * 32 + p * 16 + ((lane >> 4) << 3) + (lane & 7);
                const int seg = ks * 2 + ((lane >> 3) & 1);
                ldm_x4(b[p][0], b[p][1], b[p][2], b[p][3],
                       bbase + row * 128 + (((seg ^ (row & 7)) << 4)));
            }
            #pragma unroll
            for (int p = 0; p < 2; p++)
                #pragma unroll
                for (int mt = 0; mt < 4; mt++) {
                    hmma(acc[mt][2 * p],     a[mt][0], a[mt][1], a[mt][2], a[mt][3],
                         b[p][0], b[p][1]);
                    hmma(acc[mt][2 * p + 1], a[mt][0], a[mt][1], a[mt][2], a[mt][3],
                         b[p][2], b[p][3]);
                }
        }
    }

    // prefetch GEMM2 chunk 0 (vt) into B0 — overlaps entire loss phase.
    stage_b_async(sb + S_B0, g_vt_bf, 0, tid);
    CP_COMMIT();
    __syncthreads();   // MMA(7) LDSM reads done before partials overlay B1 / W overwrites A

    // ---- pass 1: per-row max / argmax ----
    #pragma unroll
    for (int mt = 0; mt < 4; mt++)
    #pragma unroll
    for (int h = 0; h < 2; h++) {
        const int row = mt * 16 + g + 8 * h;
        float v = -1e30f; int vi = 0;
        #pragma unroll
        for (int nt = 0; nt < 4; nt++)
        #pragma unroll
        for (int e = 0; e < 2; e++) {
            const float s = acc[mt][nt][2 * h + e];
            const int c = w * 32 + nt * 8 + tg * 2 + e;
            if (s > v) { v = s; vi = c; }
        }
        #pragma unroll
        for (int off = 1; off <= 2; off <<= 1) {
            const float v2 = __shfl_xor_sync(0xffffffffu, v, off);
            const int   i2 = __shfl_xor_sync(0xffffffffu, vi, off);
            if (v2 > v || (v2 == v && i2 < vi)) { v = v2; vi = i2; }
        }
        if (tg == 0) { s_p0[row * 16 + w] = v; s_pi[row * 16 + w] = vi; }
    }
    __syncthreads();
    if (tid < 64) {
        float v = -1e30f; int vi = 0;
        #pragma unroll
        for (int ww = 0; ww < 16; ww++) {
            const float v2 = s_p0[tid * 16 + ww];
            const int   i2 = s_pi[tid * 16 + ww];
            if (v2 > v || (v2 == v && i2 < vi)) { v = v2; vi = i2; }
        }
        s_mx[tid] = v; s_mi[tid] = vi;
    }
    __syncthreads();

    // ---- pass 2: exp, z1/z2/sw, write W bf16 tiles (same layout as A_all) ----
    #pragma unroll
    for (int mt = 0; mt < 4; mt++)
    #pragma unroll
    for (int h = 0; h < 2; h++) {
        const int row = mt * 16 + g + 8 * h;
        const float mxr = s_mx[row];
        float z1 = 0.f, z2 = 0.f, swv = 0.f;
        #pragma unroll
        for (int nt = 0; nt < 4; nt++) {
            const float s0 = acc[mt][nt][2 * h + 0];
            const float s1 = acc[mt][nt][2 * h + 1];
            const float e0 = __expf(s0 - mxr);
            const float e1 = __expf(s1 - mxr);
            z1 += e0 + e1; z2 += e0 * e0 + e1 * e1; swv += s0 * e0 + s1 * e1;
            const int seg = (w & 1) * 4 + nt;
            *(uint32_t*)(sc + S_W + (w >> 1) * 8192 + row * 128 +
                         (((seg ^ (row & 7)) << 4)) + tg * 4) = pack_bf16(e0, e1);
        }
        #pragma unroll
        for (int off = 1; off <= 2; off <<= 1) {
            z1  += __shfl_xor_sync(0xffffffffu, z1, off);
            z2  += __shfl_xor_sync(0xffffffffu, z2, off);
            swv += __shfl_xor_sync(0xffffffffu, swv, off);
        }
        if (tg == 0) {
            s_p0[row * 16 + w] = z1; s_p1[row * 16 + w] = z2; s_p2[row * 16 + w] = swv;
        }
    }
    __syncthreads();
    if (tid < 64) {
        float z1 = 0.f, z2 = 0.f, swv = 0.f;
        #pragma unroll
        for (int ww = 0; ww < 16; ww++) {
            z1 += s_p0[tid * 16 + ww]; z2 += s_p1[tid * 16 + ww]; swv += s_p2[tid * 16 + ww];
        }
        s_iz[tid] = 1.0f / z1;
        const float ent = s_mx[tid] + logf(z1) - swv / z1;
        const float con = logf(z2);
        atomicAdd(&s_acc[0], ent);
        atomicAdd(&s_acc[2], con);
    }

    // ---- gathering loss: warp w rows 4w..4w+3 ----
    {
        float gat = 0.f;
        #pragma unroll
        for (int rr = 0; rr < 4; rr++) {
            const int r = w * 4 + rr;
            const int mir = s_mi[r];
            const float4* qp = (const float4*)(query + (t0 + r) * CDIM);
            float4 qv[4]; float ssq = 0.f;
            #pragma unroll
            for (int i = 0; i < 4; i++) {
                qv[i] = qp[lane + 32 * i];
                ssq += qv[i].x * qv[i].x + qv[i].y * qv[i].y
                     + qv[i].z * qv[i].z + qv[i].w * qv[i].w;
            }
            #pragma unroll
            for (int off = 16; off; off >>= 1) ssq += __shfl_xor_sync(0xffffffffu, ssq, off);
            const float qi = 1.0f / fmaxf(sqrtf(ssq), 1e-12f);
            const float4* vp = (const float4*)(values + (size_t)mir * CDIM);
            #pragma unroll
            for (int i = 0; i < 4; i++) {
                const float4 vv = vp[lane + 32 * i];
                const float dx = qv[i].x * qi - vv.x;
                const float dy = qv[i].y * qi - vv.y;
                const float dz = qv[i].z * qi - vv.z;
                const float dw = qv[i].w * qi - vv.w;
                gat += dx * dx + dy * dy + dz * dz + dw * dw;
            }
        }
        #pragma unroll
        for (int off = 16; off; off >>= 1) gat += __shfl_xor_sync(0xffffffffu, gat, off);
        if (lane == 0) atomicAdd(&s_acc[1], gat);
    }

    // ---- GEMM2: read[64][512] = W @ values (A = W tiles resident, B pipelined) ----
    #pragma unroll
    for (int mt = 0; mt < 4; mt++)
        #pragma unroll
        for (int nt = 0; nt < 4; nt++)
            #pragma unroll
            for (int e = 0; e < 4; e++) acc[mt][nt][e] = 0.f;

    for (int mc = 0; mc < 8; mc++) {
        CP_WAIT0();
        __syncthreads();   // B chunk mc arrived; partial reads done (mc==0); prev MMA done
        if (mc < 7) {
            stage_b_async(sb + S_B0 + ((mc + 1) & 1) * 65536, g_vt_bf, mc + 1, tid);
            CP_COMMIT();
        }
        const uint32_t abase = sb + S_W + mc * 8192;
        const uint32_t bbase = sb + S_B0 + (mc & 1) * 65536;
        #pragma unroll
        for (int ks = 0; ks < 4; ks++) {
            uint32_t a[4][4];
            #pragma unroll
            for (int mt = 0; mt < 4; mt++) {
                const int row = mt * 16 + (lane & 15);
                const int seg = ks * 2 + (lane >> 4);
                ldm_x4(a[mt][0], a[mt][1], a[mt][2], a[mt][3],
                       abase + row * 128 + (((seg ^ (row & 7)) << 4)));
            }
            uint32_t b[2][4];
            #pragma unroll
            for (int p = 0; p < 2; p++) {
                const int row = w * 32 + p * 16 + ((lane >> 4) << 3) + (lane & 7);
                const int seg = ks * 2 + ((lane >> 3) & 1);
                ldm_x4(b[p][0], b[p][1], b[p][2], b[p][3],
                       bbase + row * 128 + (((seg ^ (row & 7)) << 4)));
            }
            #pragma unroll
            for (int p = 0; p < 2; p++)
                #pragma unroll
                for (int mt = 0; mt < 4; mt++) {
                    hmma(acc[mt][2 * p],     a[mt][0], a[mt][1], a[mt][2], a[mt][3],
                         b[p][0], b[p][1]);
                    hmma(acc[mt][2 * p + 1], a[mt][0], a[mt][1], a[mt][2], a[mt][3],
                         b[p][2], b[p][3]);
                }
        }
    }

    // ---- epilogue: scale by 1/z1, store ----
    #pragma unroll
    for (int mt = 0; mt < 4; mt++)
    #pragma unroll
    for (int h = 0; h < 2; h++) {
        const int row = mt * 16 + g + 8 * h;
        const float scl = s_iz[row];
        #pragma unroll
        for (int nt = 0; nt < 4; nt++) {
            const int c = w * 32 + nt * 8 + tg * 2;
            const float2 o = make_float2(acc[mt][nt][2 * h + 0] * scl,
                                         acc[mt][nt][2 * h + 1] * scl);
            *(float2*)(out_read + (t0 + row) * CDIM + c) = o;
        }
    }

    __syncthreads();
    if (tid == 0) {
        atomicAdd(out_scalars + 0, s_acc[0] * (1.0f / 32768.0f));
        atomicAdd(out_scalars + 1, s_acc[1] * (1.0f / (32768.0f * 512.0f)));
        atomicAdd(out_scalars + 2, s_acc[2] * (1.0f / 12800.0f));
    }
}

} // namespace

extern "C" void kernel_launch(void* const* d_in, const int* in_sizes, int n_in,
                              void* d_out, int out_size) {
    const float* key    = (const float*)d_in[0];
    const float* query  = (const float*)d_in[1];
    const float* keys   = (const float*)d_in[2];
    const float* values = (const float*)d_in[3];
    float* out = (float*)d_out;

    const size_t read_elems = (size_t)in_sizes[0];
    const size_t keys_elems = (size_t)in_sizes[2];
    const size_t vals_elems = (size_t)in_sizes[3];
    const long long T = (long long)(read_elems / CDIM);

    float* out_scalars = out + read_elems;
    float* out_keys    = out + read_elems + 3;
    float* out_values  = out_keys + keys_elems;

    cudaMemcpyAsync(out_keys,   keys,   keys_elems * sizeof(float), cudaMemcpyDeviceToDevice, 0);
    cudaMemcpyAsync(out_values, values, vals_elems * sizeof(float), cudaMemcpyDeviceToDevice, 0);

    zero_scalars_kernel<<<1, 32, 0, 0>>>(out_scalars);
    prep_keys_kernel<<<MDIM, 128, 0, 0>>>(keys);
    prep_vt_kernel<<<dim3(8, 8), 256, 0, 0>>>(values);

    static bool attr_set = false;
    if (!attr_set) {
        cudaFuncSetAttribute(memory_module_kernel,
                             cudaFuncAttributeMaxDynamicSharedMemorySize, SMEM_BYTES);
        attr_set = true;
    }

    const int grid = (int)(T / ROWS);   // 512
    memory_module_kernel<<<grid, NT, SMEM_BYTES, 0>>>(key, query, values,
                                                      out, out_scalars);
}

// round 15
// speedup vs baseline: 5.9267x; 1.0539x over previous
#include <cuda_runtime.h>
#include <cuda_bf16.h>
#include <cstdint>
#include <math.h>

namespace {

constexpr int CDIM = 512;
constexpr int MDIM = 512;
constexpr int ROWS = 64;     // rows per block
constexpr int NT   = 512;    // 16 warps

// SMEM byte offsets (dynamic)
constexpr int S_B0  = 0;          // B buffer 0: [512][128B] swizzled = 65536
constexpr int S_B1  = 65536;      // B buffer 1: 65536
constexpr int S_W   = 131072;     // A_all during GEMM1, W tiles after pass2 (64KB)
// partials overlaid on B1 (dead during reduction phase)
constexpr int S_P0  = 65536;      // [64][16] f32
constexpr int S_P1  = 69632;
constexpr int S_P2  = 73728;
constexpr int S_PI  = 77824;      // [64][16] i32
// persistent small arrays
constexpr int S_MX  = 196608;     // 64 f32
constexpr int S_MI  = 196864;     // 64 i32
constexpr int S_IZ  = 197120;     // 64 f32
constexpr int S_ACC = 197376;     // 3 f32
constexpr int SMEM_BYTES = 197408;

__device__ __align__(16) __nv_bfloat16 g_keys_bf[MDIM * CDIM];  // [m][c]
__device__ __align__(16) __nv_bfloat16 g_vt_bf  [CDIM * MDIM];  // [c][m]

__device__ __forceinline__ uint32_t smem_u32(const void* p) {
    uint32_t a;
    asm("{ .reg .u64 t; cvta.to.shared.u64 t, %1; cvt.u32.u64 %0, t; }" : "=r"(a) : "l"(p));
    return a;
}
__device__ __forceinline__ unsigned pack_bf16(float lo, float hi) {
    unsigned r;
    asm("cvt.rn.bf16x2.f32 %0, %1, %2;" : "=r"(r) : "f"(hi), "f"(lo));
    return r;
}
__device__ __forceinline__ void ldm_x4(uint32_t& r0, uint32_t& r1, uint32_t& r2,
                                       uint32_t& r3, uint32_t addr) {
    asm volatile("ldmatrix.sync.aligned.m8n8.x4.shared.b16 {%0,%1,%2,%3}, [%4];"
                 : "=r"(r0), "=r"(r1), "=r"(r2), "=r"(r3) : "r"(addr));
}
__device__ __forceinline__ void hmma(float* d, uint32_t a0, uint32_t a1, uint32_t a2,
                                     uint32_t a3, uint32_t b0, uint32_t b1) {
    asm volatile("mma.sync.aligned.m16n8k16.row.col.f32.bf16.bf16.f32 "
                 "{%0,%1,%2,%3}, {%4,%5,%6,%7}, {%8,%9}, {%0,%1,%2,%3};"
                 : "+f"(d[0]), "+f"(d[1]), "+f"(d[2]), "+f"(d[3])
                 : "r"(a0), "r"(a1), "r"(a2), "r"(a3), "r"(b0), "r"(b1));
}
#define CP_COMMIT() asm volatile("cp.async.commit_group;" ::: "memory")
#define CP_WAIT0()  asm volatile("cp.async.wait_group 0;" ::: "memory")

// async-stage one 512x64bf16 chunk (64KB) into swizzled [row][seg^row&7] layout
__device__ __forceinline__ void stage_b_async(uint32_t dst_base_u32,
                                              const __nv_bfloat16* gbase,
                                              int chunk, int tid) {
    const char* g = (const char*)gbase + chunk * 128;
    #pragma unroll
    for (int i = 0; i < 8; i++) {
        const int idx = tid + i * 512;
        const int m = idx >> 3, j = idx & 7;
        asm volatile("cp.async.cg.shared.global [%0], [%1], 16;"
                     :: "r"(dst_base_u32 + m * 128 + (((j ^ (m & 7)) << 4))),
                        "l"(g + (size_t)m * 1024 + j * 16) : "memory");
    }
}

// fragment loaders (swizzled 128B-row tiles)
__device__ __forceinline__ void load_a_frags(uint32_t (&f)[4][4], uint32_t abase,
                                             int ks, int lane) {
    #pragma unroll
    for (int mt = 0; mt < 4; mt++) {
        const int row = mt * 16 + (lane & 15);
        const int seg = ks * 2 + (lane >> 4);
        ldm_x4(f[mt][0], f[mt][1], f[mt][2], f[mt][3],
               abase + row * 128 + (((seg ^ (row & 7)) << 4)));
    }
}
__device__ __forceinline__ void load_b_frags(uint32_t (&f)[2][4], uint32_t bbase,
                                             int ks, int lane, int w) {
    #pragma unroll
    for (int p = 0; p < 2; p++) {
        const int row = w * 32 + p * 16 + ((lane >> 4) << 3) + (lane & 7);
        const int seg = ks * 2 + ((lane >> 3) & 1);
        ldm_x4(f[p][0], f[p][1], f[p][2], f[p][3],
               bbase + row * 128 + (((seg ^ (row & 7)) << 4)));
    }
}
__device__ __forceinline__ void mma_tile(float (&acc)[4][4][4],
                                         const uint32_t (&fa)[4][4],
                                         const uint32_t (&fb)[2][4]) {
    #pragma unroll
    for (int p = 0; p < 2; p++)
        #pragma unroll
        for (int mt = 0; mt < 4; mt++) {
            hmma(acc[mt][2 * p],     fa[mt][0], fa[mt][1], fa[mt][2], fa[mt][3],
                 fb[p][0], fb[p][1]);
            hmma(acc[mt][2 * p + 1], fa[mt][0], fa[mt][1], fa[mt][2], fa[mt][3],
                 fb[p][2], fb[p][3]);
        }
}

// ---- combined prep: keys->bf16, vt->bf16, passthrough copies, zero scalars ----
// NOTE: out_keys / out_values are only 4-byte aligned (base + odd float offset),
// so passthrough stores MUST be scalar floats, never float2/float4.
__global__ void prep_kernel(const float* __restrict__ keys,
                            const float* __restrict__ values,
                            float* __restrict__ out_keys,
                            float* __restrict__ out_values,
                            float* __restrict__ scalars) {
    const int bx = blockIdx.x;   // 64 blocks
    const int t  = threadIdx.x;  // 256 threads
    if (bx == 0 && t < 3) scalars[t] = 0.0f;

    // keys rows bx*8 .. +7 : bf16 convert + passthrough copy (scalar stores)
    {
        const float4* src = (const float4*)(keys + (size_t)bx * 8 * CDIM);
        float* ok = out_keys + (size_t)bx * 8 * CDIM;
        uint2* dst = (uint2*)(g_keys_bf + (size_t)bx * 8 * CDIM);
        #pragma unroll
        for (int i = 0; i < 4; i++) {
            const int idx = t + i * 256;            // 0..1023 float4s
            const float4 v = src[idx];
            ok[idx * 4 + 0] = v.x; ok[idx * 4 + 1] = v.y;
            ok[idx * 4 + 2] = v.z; ok[idx * 4 + 3] = v.w;
            dst[idx] = make_uint2(pack_bf16(v.x, v.y), pack_bf16(v.z, v.w));
        }
    }

    // values tile transpose: m0=(bx>>3)*64, c0=(bx&7)*64 + passthrough copy
    __shared__ float tile[64][65];
    const int m0 = (bx >> 3) * 64, c0 = (bx & 7) * 64;
    #pragma unroll
    for (int i = 0; i < 4; i++) {
        const int idx = t + i * 256;
        const int ml = idx >> 4, cp = idx & 15;
        const float4 v = ((const float4*)(values + (size_t)(m0 + ml) * CDIM + c0))[cp];
        float* ov = out_values + (size_t)(m0 + ml) * CDIM + c0 + cp * 4;
        ov[0] = v.x; ov[1] = v.y; ov[2] = v.z; ov[3] = v.w;
        tile[ml][cp * 4 + 0] = v.x; tile[ml][cp * 4 + 1] = v.y;
        tile[ml][cp * 4 + 2] = v.z; tile[ml][cp * 4 + 3] = v.w;
    }
    __syncthreads();
    #pragma unroll
    for (int i = 0; i < 4; i++) {
        const int idx = t + i * 256;
        const int cl = idx >> 4, jp = (idx & 15) * 4;
        ((uint2*)(g_vt_bf + (size_t)(c0 + cl) * MDIM + m0))[idx & 15] =
            make_uint2(pack_bf16(tile[jp + 0][cl], tile[jp + 1][cl]),
                       pack_bf16(tile[jp + 2][cl], tile[jp + 3][cl]));
    }
}

__global__ __launch_bounds__(NT, 1)
void memory_module_kernel(const float* __restrict__ key,
                          const float* __restrict__ query,
                          const float* __restrict__ values,
                          float* __restrict__ out_read,
                          float* __restrict__ out_scalars) {
    extern __shared__ char sc[];
    const uint32_t sb = smem_u32(sc);
    const int tid = threadIdx.x;
    const int lane = tid & 31, w = tid >> 5;       // 16 warps
    const int g = lane >> 2, tg = lane & 3;
    const size_t t0 = (size_t)blockIdx.x * ROWS;

    float* s_p0 = (float*)(sc + S_P0);
    float* s_p1 = (float*)(sc + S_P1);
    float* s_p2 = (float*)(sc + S_P2);
    int*   s_pi = (int*)  (sc + S_PI);
    float* s_mx = (float*)(sc + S_MX);
    int*   s_mi = (int*)  (sc + S_MI);
    float* s_iz = (float*)(sc + S_IZ);
    float* s_acc= (float*)(sc + S_ACC);

    if (tid < 3) s_acc[tid] = 0.f;

    // prefetch GEMM1 chunk 0 B tile (overlaps norm phase)
    stage_b_async(sb + S_B0, g_keys_bf, 0, tid);
    CP_COMMIT();

    // ---- norm phase: normalize key rows, write bf16 A_all (chunked swizzled) ----
    #pragma unroll
    for (int rr = 0; rr < 4; rr++) {
        const int r = w * 4 + rr;
        const float4* kp = (const float4*)(key + (t0 + r) * CDIM);
        float4 v[4];
        float ss = 0.f;
        #pragma unroll
        for (int i = 0; i < 4; i++) {
            v[i] = kp[lane + 32 * i];
            ss += v[i].x * v[i].x + v[i].y * v[i].y + v[i].z * v[i].z + v[i].w * v[i].w;
        }
        #pragma unroll
        for (int off = 16; off; off >>= 1) ss += __shfl_xor_sync(0xffffffffu, ss, off);
        const float inv = 1.0f / fmaxf(sqrtf(ss), 1e-12f);
        #pragma unroll
        for (int i = 0; i < 4; i++) {
            const int c0 = (lane + 32 * i) * 4;
            const int cin = c0 & 63;
            *(uint2*)(sc + S_W + (c0 >> 6) * 8192 + r * 128 +
                      ((((cin >> 3) ^ (r & 7)) << 4)) + ((cin & 7) * 2)) =
                make_uint2(pack_bf16(v[i].x * inv, v[i].y * inv),
                           pack_bf16(v[i].z * inv, v[i].w * inv));
        }
    }
    __syncthreads();

    float acc[4][4][4];
    #pragma unroll
    for (int mt = 0; mt < 4; mt++)
        #pragma unroll
        for (int nt = 0; nt < 4; nt++)
            #pragma unroll
            for (int e = 0; e < 4; e++) acc[mt][nt][e] = 0.f;

    // ---- GEMM1: score[64][512] = khat @ keys^T (sw-pipelined ks loop) ----
    for (int kc = 0; kc < 8; kc++) {
        CP_WAIT0();
        __syncthreads();   // B chunk kc arrived; prev MMA done
        if (kc < 7) {
            stage_b_async(sb + S_B0 + ((kc + 1) & 1) * 65536, g_keys_bf, kc + 1, tid);
            CP_COMMIT();
        }
        const uint32_t abase = sb + S_W + kc * 8192;
        const uint32_t bbase = sb + S_B0 + (kc & 1) * 65536;
        uint32_t fa[2][4][4], fb[2][2][4];
        load_a_frags(fa[0], abase, 0, lane);
        load_b_frags(fb[0], bbase, 0, lane, w);
        #pragma unroll
        for (int ks = 0; ks < 4; ks++) {
            if (ks < 3) {
                load_a_frags(fa[(ks + 1) & 1], abase, ks + 1, lane);
                load_b_frags(fb[(ks + 1) & 1], bbase, ks + 1, lane, w);
            }
            mma_tile(acc, fa[ks & 1], fb[ks & 1]);
        }
    }

    // prefetch GEMM2 chunk 0 (vt) into B0 — overlaps entire loss phase.
    stage_b_async(sb + S_B0, g_vt_bf, 0, tid);
    CP_COMMIT();
    __syncthreads();   // MMA(7) LDSM reads done before partials overlay B1 / W overwrites A

    // ---- pass 1: per-row max / argmax ----
    #pragma unroll
    for (int mt = 0; mt < 4; mt++)
    #pragma unroll
    for (int h = 0; h < 2; h++) {
        const int row = mt * 16 + g + 8 * h;
        float v = -1e30f; int vi = 0;
        #pragma unroll
        for (int nt = 0; nt < 4; nt++)
        #pragma unroll
        for (int e = 0; e < 2; e++) {
            const float s = acc[mt][nt][2 * h + e];
            const int c = w * 32 + nt * 8 + tg * 2 + e;
            if (s > v) { v = s; vi = c; }
        }
        #pragma unroll
        for (int off = 1; off <= 2; off <<= 1) {
            const float v2 = __shfl_xor_sync(0xffffffffu, v, off);
            const int   i2 = __shfl_xor_sync(0xffffffffu, vi, off);
            if (v2 > v || (v2 == v && i2 < vi)) { v = v2; vi = i2; }
        }
        if (tg == 0) { s_p0[row * 16 + w] = v; s_pi[row * 16 + w] = vi; }
    }
    __syncthreads();
    if (tid < 64) {
        float v = -1e30f; int vi = 0;
        #pragma unroll
        for (int ww = 0; ww < 16; ww++) {
            const float v2 = s_p0[tid * 16 + ww];
            const int   i2 = s_pi[tid * 16 + ww];
            if (v2 > v || (v2 == v && i2 < vi)) { v = v2; vi = i2; }
        }
        s_mx[tid] = v; s_mi[tid] = vi;
    }
    __syncthreads();

    // ---- pass 2: exp, z1/z2/sw, write W bf16 tiles (same layout as A_all) ----
    #pragma unroll
    for (int mt = 0; mt < 4; mt++)
    #pragma unroll
    for (int h = 0; h < 2; h++) {
        const int row = mt * 16 + g + 8 * h;
        const float mxr = s_mx[row];
        float z1 = 0.f, z2 = 0.f, swv = 0.f;
        #pragma unroll
        for (int nt = 0; nt < 4; nt++) {
            const float s0 = acc[mt][nt][2 * h + 0];
            const float s1 = acc[mt][nt][2 * h + 1];
            const float e0 = __expf(s0 - mxr);
            const float e1 = __expf(s1 - mxr);
            z1 += e0 + e1; z2 += e0 * e0 + e1 * e1; swv += s0 * e0 + s1 * e1;
            const int seg = (w & 1) * 4 + nt;
            *(uint32_t*)(sc + S_W + (w >> 1) * 8192 + row * 128 +
                         (((seg ^ (row & 7)) << 4)) + tg * 4) = pack_bf16(e0, e1);
        }
        #pragma unroll
        for (int off = 1; off <= 2; off <<= 1) {
            z1  += __shfl_xor_sync(0xffffffffu, z1, off);
            z2  += __shfl_xor_sync(0xffffffffu, z2, off);
            swv += __shfl_xor_sync(0xffffffffu, swv, off);
        }
        if (tg == 0) {
            s_p0[row * 16 + w] = z1; s_p1[row * 16 + w] = z2; s_p2[row * 16 + w] = swv;
        }
    }
    __syncthreads();
    if (tid < 64) {
        float z1 = 0.f, z2 = 0.f, swv = 0.f;
        #pragma unroll
        for (int ww = 0; ww < 16; ww++) {
            z1 += s_p0[tid * 16 + ww]; z2 += s_p1[tid * 16 + ww]; swv += s_p2[tid * 16 + ww];
        }
        s_iz[tid] = 1.0f / z1;
        const float ent = s_mx[tid] + logf(z1) - swv / z1;
        const float con = logf(z2);
        atomicAdd(&s_acc[0], ent);
        atomicAdd(&s_acc[2], con);
    }

    // ---- gathering loss: warp w rows 4w..4w+3 ----
    {
        float gat = 0.f;
        #pragma unroll
        for (int rr = 0; rr < 4; rr++) {
            const int r = w * 4 + rr;
            const int mir = s_mi[r];
            const float4* qp = (const float4*)(query + (t0 + r) * CDIM);
            float4 qv[4]; float ssq = 0.f;
            #pragma unroll
            for (int i = 0; i < 4; i++) {
                qv[i] = qp[lane + 32 * i];
                ssq += qv[i].x * qv[i].x + qv[i].y * qv[i].y
                     + qv[i].z * qv[i].z + qv[i].w * qv[i].w;
            }
            #pragma unroll
            for (int off = 16; off; off >>= 1) ssq += __shfl_xor_sync(0xffffffffu, ssq, off);
            const float qi = 1.0f / fmaxf(sqrtf(ssq), 1e-12f);
            const float4* vp = (const float4*)(values + (size_t)mir * CDIM);
            #pragma unroll
            for (int i = 0; i < 4; i++) {
                const float4 vv = vp[lane + 32 * i];
                const float dx = qv[i].x * qi - vv.x;
                const float dy = qv[i].y * qi - vv.y;
                const float dz = qv[i].z * qi - vv.z;
                const float dw = qv[i].w * qi - vv.w;
                gat += dx * dx + dy * dy + dz * dz + dw * dw;
            }
        }
        #pragma unroll
        for (int off = 16; off; off >>= 1) gat += __shfl_xor_sync(0xffffffffu, gat, off);
        if (lane == 0) atomicAdd(&s_acc[1], gat);
    }

    // ---- GEMM2: read[64][512] = W @ values (sw-pipelined ks loop) ----
    #pragma unroll
    for (int mt = 0; mt < 4; mt++)
        #pragma unroll
        for (int nt = 0; nt < 4; nt++)
            #pragma unroll
            for (int e = 0; e < 4; e++) acc[mt][nt][e] = 0.f;

    for (int mc = 0; mc < 8; mc++) {
        CP_WAIT0();
        __syncthreads();   // B chunk mc arrived; partial reads done; prev MMA done
        if (mc < 7) {
            stage_b_async(sb + S_B0 + ((mc + 1) & 1) * 65536, g_vt_bf, mc + 1, tid);
            CP_COMMIT();
        }
        const uint32_t abase = sb + S_W + mc * 8192;
        const uint32_t bbase = sb + S_B0 + (mc & 1) * 65536;
        uint32_t fa[2][4][4], fb[2][2][4];
        load_a_frags(fa[0], abase, 0, lane);
        load_b_frags(fb[0], bbase, 0, lane, w);
        #pragma unroll
        for (int ks = 0; ks < 4; ks++) {
            if (ks < 3) {
                load_a_frags(fa[(ks + 1) & 1], abase, ks + 1, lane);
                load_b_frags(fb[(ks + 1) & 1], bbase, ks + 1, lane, w);
            }
            mma_tile(acc, fa[ks & 1], fb[ks & 1]);
        }
    }

    // ---- epilogue: scale by 1/z1, store ----
    #pragma unroll
    for (int mt = 0; mt < 4; mt++)
    #pragma unroll
    for (int h = 0; h < 2; h++) {
        const int row = mt * 16 + g + 8 * h;
        const float scl = s_iz[row];
        #pragma unroll
        for (int nt = 0; nt < 4; nt++) {
            const int c = w * 32 + nt * 8 + tg * 2;
            const float2 o = make_float2(acc[mt][nt][2 * h + 0] * scl,
                                         acc[mt][nt][2 * h + 1] * scl);
            *(float2*)(out_read + (t0 + row) * CDIM + c) = o;
        }
    }

    __syncthreads();
    if (tid == 0) {
        atomicAdd(out_scalars + 0, s_acc[0] * (1.0f / 32768.0f));
        atomicAdd(out_scalars + 1, s_acc[1] * (1.0f / (32768.0f * 512.0f)));
        atomicAdd(out_scalars + 2, s_acc[2] * (1.0f / 12800.0f));
    }
}

} // namespace

extern "C" void kernel_launch(void* const* d_in, const int* in_sizes, int n_in,
                              void* d_out, int out_size) {
    const float* key    = (const float*)d_in[0];
    const float* query  = (const float*)d_in[1];
    const float* keys   = (const float*)d_in[2];
    const float* values = (const float*)d_in[3];
    float* out = (float*)d_out;

    const size_t read_elems = (size_t)in_sizes[0];
    const size_t keys_elems = (size_t)in_sizes[2];
    const long long T = (long long)(read_elems / CDIM);

    float* out_scalars = out + read_elems;
    float* out_keys    = out + read_elems + 3;
    float* out_values  = out_keys + keys_elems;

    // single prep kernel: bf16 conversions + passthrough copies + scalar zeroing
    prep_kernel<<<64, 256, 0, 0>>>(keys, values, out_keys, out_values, out_scalars);

    static bool attr_set = false;
    if (!attr_set) {
        cudaFuncSetAttribute(memory_module_kernel,
                             cudaFuncAttributeMaxDynamicSharedMemorySize, SMEM_BYTES);
        attr_set = true;
    }

    const int grid = (int)(T / ROWS);   // 512
    memory_module_kernel<<<grid, NT, SMEM_BYTES, 0>>>(key, query, values,
                                                      out, out_scalars);
}

// round 16
// speedup vs baseline: 6.1415x; 1.0362x over previous
#include <cuda_runtime.h>
#include <cuda_bf16.h>
#include <cstdint>
#include <math.h>

namespace {

constexpr int CDIM = 512;
constexpr int MDIM = 512;
constexpr int ROWS = 64;     // rows per block
constexpr int NT   = 512;    // 16 warps

// SMEM byte offsets (dynamic)
constexpr int S_B0  = 0;          // B buffer 0: [512][128B] swizzled = 65536
constexpr int S_B1  = 65536;      // B buffer 1: 65536
constexpr int S_W   = 131072;     // A_all during GEMM1, W tiles after softmax (64KB)
// partials overlaid on B1 (dead during reduction phase)
constexpr int S_P0  = 65536;      // [64][16] f32  z1
constexpr int S_P1  = 69632;      //               z2
constexpr int S_P2  = 73728;      //               sw
constexpr int S_PI  = 77824;      // [64][16] i32  argmax
constexpr int S_P3  = 81920;      // [64][16] f32  max
// persistent small arrays
constexpr int S_MI  = 196608;     // 64 i32
constexpr int S_IZ  = 196864;     // 64 f32
constexpr int S_QI  = 197120;     // 64 f32 (query inv-norms)
constexpr int S_ACC = 197376;     // 3 f32
constexpr int SMEM_BYTES = 197408;

__device__ __align__(16) __nv_bfloat16 g_keys_bf[MDIM * CDIM];  // [m][c]
__device__ __align__(16) __nv_bfloat16 g_vt_bf  [CDIM * MDIM];  // [c][m]

__device__ __forceinline__ uint32_t smem_u32(const void* p) {
    uint32_t a;
    asm("{ .reg .u64 t; cvta.to.shared.u64 t, %1; cvt.u32.u64 %0, t; }" : "=r"(a) : "l"(p));
    return a;
}
__device__ __forceinline__ unsigned pack_bf16(float lo, float hi) {
    unsigned r;
    asm("cvt.rn.bf16x2.f32 %0, %1, %2;" : "=r"(r) : "f"(hi), "f"(lo));
    return r;
}
__device__ __forceinline__ void ldm_x4(uint32_t& r0, uint32_t& r1, uint32_t& r2,
                                       uint32_t& r3, uint32_t addr) {
    asm volatile("ldmatrix.sync.aligned.m8n8.x4.shared.b16 {%0,%1,%2,%3}, [%4];"
                 : "=r"(r0), "=r"(r1), "=r"(r2), "=r"(r3) : "r"(addr));
}
__device__ __forceinline__ void hmma(float* d, uint32_t a0, uint32_t a1, uint32_t a2,
                                     uint32_t a3, uint32_t b0, uint32_t b1) {
    asm volatile("mma.sync.aligned.m16n8k16.row.col.f32.bf16.bf16.f32 "
                 "{%0,%1,%2,%3}, {%4,%5,%6,%7}, {%8,%9}, {%0,%1,%2,%3};"
                 : "+f"(d[0]), "+f"(d[1]), "+f"(d[2]), "+f"(d[3])
                 : "r"(a0), "r"(a1), "r"(a2), "r"(a3), "r"(b0), "r"(b1));
}
#define CP_COMMIT() asm volatile("cp.async.commit_group;" ::: "memory")
#define CP_WAIT0()  asm volatile("cp.async.wait_group 0;" ::: "memory")

// async-stage one 512x64bf16 chunk (64KB) into swizzled [row][seg^row&7] layout
__device__ __forceinline__ void stage_b_async(uint32_t dst_base_u32,
                                              const __nv_bfloat16* gbase,
                                              int chunk, int tid) {
    const char* g = (const char*)gbase + chunk * 128;
    #pragma unroll
    for (int i = 0; i < 8; i++) {
        const int idx = tid + i * 512;
        const int m = idx >> 3, j = idx & 7;
        asm volatile("cp.async.cg.shared.global [%0], [%1], 16;"
                     :: "r"(dst_base_u32 + m * 128 + (((j ^ (m & 7)) << 4))),
                        "l"(g + (size_t)m * 1024 + j * 16) : "memory");
    }
}

// fragment loaders (swizzled 128B-row tiles)
__device__ __forceinline__ void load_a_frags(uint32_t (&f)[4][4], uint32_t abase,
                                             int ks, int lane) {
    #pragma unroll
    for (int mt = 0; mt < 4; mt++) {
        const int row = mt * 16 + (lane & 15);
        const int seg = ks * 2 + (lane >> 4);
        ldm_x4(f[mt][0], f[mt][1], f[mt][2], f[mt][3],
               abase + row * 128 + (((seg ^ (row & 7)) << 4)));
    }
}
__device__ __forceinline__ void load_b_frags(uint32_t (&f)[2][4], uint32_t bbase,
                                             int ks, int lane, int w) {
    #pragma unroll
    for (int p = 0; p < 2; p++) {
        const int row = w * 32 + p * 16 + ((lane >> 4) << 3) + (lane & 7);
        const int seg = ks * 2 + ((lane >> 3) & 1);
        ldm_x4(f[p][0], f[p][1], f[p][2], f[p][3],
               bbase + row * 128 + (((seg ^ (row & 7)) << 4)));
    }
}
__device__ __forceinline__ void mma_tile(float (&acc)[4][4][4],
                                         const uint32_t (&fa)[4][4],
                                         const uint32_t (&fb)[2][4]) {
    #pragma unroll
    for (int p = 0; p < 2; p++)
        #pragma unroll
        for (int mt = 0; mt < 4; mt++) {
            hmma(acc[mt][2 * p],     fa[mt][0], fa[mt][1], fa[mt][2], fa[mt][3],
                 fb[p][0], fb[p][1]);
            hmma(acc[mt][2 * p + 1], fa[mt][0], fa[mt][1], fa[mt][2], fa[mt][3],
                 fb[p][2], fb[p][3]);
        }
}

// ---- combined prep (256 blocks x 256 thr): keys->bf16, vt->bf16, passthrough ----
// NOTE: out_keys / out_values are only 4-byte aligned -> scalar float stores only.
__global__ void prep_kernel(const float* __restrict__ keys,
                            const float* __restrict__ values,
                            float* __restrict__ out_keys,
                            float* __restrict__ out_values,
                            float* __restrict__ scalars) {
    const int bx = blockIdx.x;   // 256 blocks
    const int t  = threadIdx.x;  // 256 threads
    if (bx == 0 && t < 3) scalars[t] = 0.0f;

    // keys: 2 rows per block (rows bx*2, bx*2+1)
    {
        const float4* src = (const float4*)(keys + (size_t)bx * 2 * CDIM);
        float* ok = out_keys + (size_t)bx * 2 * CDIM;
        uint2* dst = (uint2*)(g_keys_bf + (size_t)bx * 2 * CDIM);
        const float4 v = src[t];
        ok[t * 4 + 0] = v.x; ok[t * 4 + 1] = v.y;
        ok[t * 4 + 2] = v.z; ok[t * 4 + 3] = v.w;
        dst[t] = make_uint2(pack_bf16(v.x, v.y), pack_bf16(v.z, v.w));
    }

    // values^T quarter-tile: tile = bx>>2 (m0,c0), quarter q = bx&3 (16 m-rows)
    __shared__ float tl[16][65];
    const int tile = bx >> 2, q = bx & 3;
    const int m0 = (tile >> 3) * 64, c0 = (tile & 7) * 64;
    const int mq = m0 + q * 16;
    {
        const int ml = t >> 4, cp = t & 15;
        const float4 v = ((const float4*)(values + (size_t)(mq + ml) * CDIM + c0))[cp];
        float* ov = out_values + (size_t)(mq + ml) * CDIM + c0 + cp * 4;
        ov[0] = v.x; ov[1] = v.y; ov[2] = v.z; ov[3] = v.w;
        tl[ml][cp * 4 + 0] = v.x; tl[ml][cp * 4 + 1] = v.y;
        tl[ml][cp * 4 + 2] = v.z; tl[ml][cp * 4 + 3] = v.w;
    }
    __syncthreads();
    {
        const int cl = t >> 2, jp = (t & 3) * 4;
        ((uint2*)(g_vt_bf + (size_t)(c0 + cl) * MDIM + mq))[t & 3] =
            make_uint2(pack_bf16(tl[jp + 0][cl], tl[jp + 1][cl]),
                       pack_bf16(tl[jp + 2][cl], tl[jp + 3][cl]));
    }
}

__global__ __launch_bounds__(NT, 1)
void memory_module_kernel(const float* __restrict__ key,
                          const float* __restrict__ query,
                          const float* __restrict__ values,
                          float* __restrict__ out_read,
                          float* __restrict__ out_scalars) {
    extern __shared__ char sc[];
    const uint32_t sb = smem_u32(sc);
    const int tid = threadIdx.x;
    const int lane = tid & 31, w = tid >> 5;       // 16 warps
    const int g = lane >> 2, tg = lane & 3;
    const size_t t0 = (size_t)blockIdx.x * ROWS;

    float* s_p0 = (float*)(sc + S_P0);
    float* s_p1 = (float*)(sc + S_P1);
    float* s_p2 = (float*)(sc + S_P2);
    int*   s_pi = (int*)  (sc + S_PI);
    float* s_p3 = (float*)(sc + S_P3);
    int*   s_mi = (int*)  (sc + S_MI);
    float* s_iz = (float*)(sc + S_IZ);
    float* s_qi = (float*)(sc + S_QI);
    float* s_acc= (float*)(sc + S_ACC);

    if (tid < 3) s_acc[tid] = 0.f;

    // prefetch GEMM1 chunk 0 B tile (overlaps norm phase)
    stage_b_async(sb + S_B0, g_keys_bf, 0, tid);
    CP_COMMIT();

    // ---- norm phase: key rows -> bf16 A_all; query inv-norms -> s_qi ----
    #pragma unroll
    for (int rr = 0; rr < 4; rr++) {
        const int r = w * 4 + rr;
        const float4* kp = (const float4*)(key + (t0 + r) * CDIM);
        const float4* qp = (const float4*)(query + (t0 + r) * CDIM);
        float4 v[4];
        float ss = 0.f, ssq = 0.f;
        #pragma unroll
        for (int i = 0; i < 4; i++) {
            v[i] = kp[lane + 32 * i];
            const float4 qv = qp[lane + 32 * i];
            ss  += v[i].x * v[i].x + v[i].y * v[i].y + v[i].z * v[i].z + v[i].w * v[i].w;
            ssq += qv.x * qv.x + qv.y * qv.y + qv.z * qv.z + qv.w * qv.w;
        }
        #pragma unroll
        for (int off = 16; off; off >>= 1) {
            ss  += __shfl_xor_sync(0xffffffffu, ss, off);
            ssq += __shfl_xor_sync(0xffffffffu, ssq, off);
        }
        const float inv = 1.0f / fmaxf(sqrtf(ss), 1e-12f);
        if (lane == 0) s_qi[r] = 1.0f / fmaxf(sqrtf(ssq), 1e-12f);
        #pragma unroll
        for (int i = 0; i < 4; i++) {
            const int c0 = (lane + 32 * i) * 4;
            const int cin = c0 & 63;
            *(uint2*)(sc + S_W + (c0 >> 6) * 8192 + r * 128 +
                      ((((cin >> 3) ^ (r & 7)) << 4)) + ((cin & 7) * 2)) =
                make_uint2(pack_bf16(v[i].x * inv, v[i].y * inv),
                           pack_bf16(v[i].z * inv, v[i].w * inv));
        }
    }
    __syncthreads();

    float acc[4][4][4];
    #pragma unroll
    for (int mt = 0; mt < 4; mt++)
        #pragma unroll
        for (int nt = 0; nt < 4; nt++)
            #pragma unroll
            for (int e = 0; e < 4; e++) acc[mt][nt][e] = 0.f;

    // ---- GEMM1: score[64][512] = khat @ keys^T (sw-pipelined ks loop) ----
    for (int kc = 0; kc < 8; kc++) {
        CP_WAIT0();
        __syncthreads();   // B chunk kc arrived; prev MMA done
        if (kc < 7) {
            stage_b_async(sb + S_B0 + ((kc + 1) & 1) * 65536, g_keys_bf, kc + 1, tid);
            CP_COMMIT();
        }
        const uint32_t abase = sb + S_W + kc * 8192;
        const uint32_t bbase = sb + S_B0 + (kc & 1) * 65536;
        uint32_t fa[2][4][4], fb[2][2][4];
        load_a_frags(fa[0], abase, 0, lane);
        load_b_frags(fb[0], bbase, 0, lane, w);
        #pragma unroll
        for (int ks = 0; ks < 4; ks++) {
            if (ks < 3) {
                load_a_frags(fa[(ks + 1) & 1], abase, ks + 1, lane);
                load_b_frags(fb[(ks + 1) & 1], bbase, ks + 1, lane, w);
            }
            mma_tile(acc, fa[ks & 1], fb[ks & 1]);
        }
    }

    // prefetch GEMM2 chunk 0 (vt) into B0 — overlaps entire loss phase.
    stage_b_async(sb + S_B0, g_vt_bf, 0, tid);
    CP_COMMIT();
    __syncthreads();   // MMA(7) LDSM reads done before partials overlay B1 / W overwrites A

    // ---- single merged softmax pass: exp (no shift), z1/z2/sw, max/argmax, W ----
    // Safe unshifted: |score| <= ~2 (unit khat, keys in [0,1]).
    #pragma unroll
    for (int mt = 0; mt < 4; mt++)
    #pragma unroll
    for (int h = 0; h < 2; h++) {
        const int row = mt * 16 + g + 8 * h;
        float mxv = -1e30f; int mxi = 0;
        float z1 = 0.f, z2 = 0.f, swv = 0.f;
        #pragma unroll
        for (int nt = 0; nt < 4; nt++) {
            const float s0 = acc[mt][nt][2 * h + 0];
            const float s1 = acc[mt][nt][2 * h + 1];
            const float e0 = __expf(s0);
            const float e1 = __expf(s1);
            z1 += e0 + e1; z2 += e0 * e0 + e1 * e1; swv += s0 * e0 + s1 * e1;
            const int c = w * 32 + nt * 8 + tg * 2;
            if (s0 > mxv) { mxv = s0; mxi = c; }
            if (s1 > mxv) { mxv = s1; mxi = c + 1; }
            const int seg = (w & 1) * 4 + nt;
            *(uint32_t*)(sc + S_W + (w >> 1) * 8192 + row * 128 +
                         (((seg ^ (row & 7)) << 4)) + tg * 4) = pack_bf16(e0, e1);
        }
        #pragma unroll
        for (int off = 1; off <= 2; off <<= 1) {
            z1  += __shfl_xor_sync(0xffffffffu, z1, off);
            z2  += __shfl_xor_sync(0xffffffffu, z2, off);
            swv += __shfl_xor_sync(0xffffffffu, swv, off);
            const float v2 = __shfl_xor_sync(0xffffffffu, mxv, off);
            const int   i2 = __shfl_xor_sync(0xffffffffu, mxi, off);
            if (v2 > mxv || (v2 == mxv && i2 < mxi)) { mxv = v2; mxi = i2; }
        }
        if (tg == 0) {
            s_p0[row * 16 + w] = z1; s_p1[row * 16 + w] = z2; s_p2[row * 16 + w] = swv;
            s_p3[row * 16 + w] = mxv; s_pi[row * 16 + w] = mxi;
        }
    }
    __syncthreads();

    // ---- parallel distributed reductions ----
    if (w < 4) {
        // warps 0-3: z1/z2/sw (2 threads per row, 8 partials each)
        const int row = tid >> 1, h = tid & 1;
        float z1 = 0.f, z2 = 0.f, swv = 0.f;
        #pragma unroll
        for (int i = 0; i < 8; i++) {
            const int ww = h * 8 + i;
            z1 += s_p0[row * 16 + ww]; z2 += s_p1[row * 16 + ww]; swv += s_p2[row * 16 + ww];
        }
        z1  += __shfl_xor_sync(0xffffffffu, z1, 1);
        z2  += __shfl_xor_sync(0xffffffffu, z2, 1);
        swv += __shfl_xor_sync(0xffffffffu, swv, 1);
        float ent = 0.f, c2 = 0.f;
        if (h == 0) {
            s_iz[row] = 1.0f / z1;
            ent = logf(z1) - swv / z1;     // mx cancels in entropy
            c2  = logf(z2);
        }
        #pragma unroll
        for (int off = 1; off < 32; off <<= 1) {
            ent += __shfl_xor_sync(0xffffffffu, ent, off);
            c2  += __shfl_xor_sync(0xffffffffu, c2, off);
        }
        if (lane == 0) { atomicAdd(&s_acc[0], ent); atomicAdd(&s_acc[2], c2); }
    } else if (w < 8) {
        // warps 4-7: max/argmax (2 threads per row)
        const int t2 = tid - 128;
        const int row = t2 >> 1, h = t2 & 1;
        float v = -1e30f; int vi = 0;
        #pragma unroll
        for (int i = 0; i < 8; i++) {
            const int ww = h * 8 + i;
            const float v2 = s_p3[row * 16 + ww];
            const int   i2 = s_pi[row * 16 + ww];
            if (v2 > v || (v2 == v && i2 < vi)) { v = v2; vi = i2; }
        }
        {
            const float v2 = __shfl_xor_sync(0xffffffffu, v, 1);
            const int   i2 = __shfl_xor_sync(0xffffffffu, vi, 1);
            if (v2 > v || (v2 == v && i2 < vi)) { v = v2; vi = i2; }
        }
        float conm = 0.f;
        if (h == 0) {
            s_mi[row] = vi;
            conm = -2.0f * v;              // contrast: log z2 - 2*mx per row
        }
        #pragma unroll
        for (int off = 1; off < 32; off <<= 1)
            conm += __shfl_xor_sync(0xffffffffu, conm, off);
        if (lane == 0) atomicAdd(&s_acc[2], conm);
    }
    __syncthreads();

    // ---- gathering loss: warp w rows 4w..4w+3 (query re-read is L2-hot) ----
    {
        float gat = 0.f;
        #pragma unroll
        for (int rr = 0; rr < 4; rr++) {
            const int r = w * 4 + rr;
            const int mir = s_mi[r];
            const float qi = s_qi[r];
            const float4* qp = (const float4*)(query + (t0 + r) * CDIM);
            const float4* vp = (const float4*)(values + (size_t)mir * CDIM);
            #pragma unroll
            for (int i = 0; i < 4; i++) {
                const float4 qv = qp[lane + 32 * i];
                const float4 vv = vp[lane + 32 * i];
                const float dx = qv.x * qi - vv.x;
                const float dy = qv.y * qi - vv.y;
                const float dz = qv.z * qi - vv.z;
                const float dw = qv.w * qi - vv.w;
                gat += dx * dx + dy * dy + dz * dz + dw * dw;
            }
        }
        #pragma unroll
        for (int off = 16; off; off >>= 1) gat += __shfl_xor_sync(0xffffffffu, gat, off);
        if (lane == 0) atomicAdd(&s_acc[1], gat);
    }

    // ---- GEMM2: read[64][512] = W @ values (sw-pipelined ks loop) ----
    #pragma unroll
    for (int mt = 0; mt < 4; mt++)
        #pragma unroll
        for (int nt = 0; nt < 4; nt++)
            #pragma unroll
            for (int e = 0; e < 4; e++) acc[mt][nt][e] = 0.f;

    for (int mc = 0; mc < 8; mc++) {
        CP_WAIT0();
        __syncthreads();   // B chunk mc arrived; partial reads done; prev MMA done
        if (mc < 7) {
            stage_b_async(sb + S_B0 + ((mc + 1) & 1) * 65536, g_vt_bf, mc + 1, tid);
            CP_COMMIT();
        }
        const uint32_t abase = sb + S_W + mc * 8192;
        const uint32_t bbase = sb + S_B0 + (mc & 1) * 65536;
        uint32_t fa[2][4][4], fb[2][2][4];
        load_a_frags(fa[0], abase, 0, lane);
        load_b_frags(fb[0], bbase, 0, lane, w);
        #pragma unroll
        for (int ks = 0; ks < 4; ks++) {
            if (ks < 3) {
                load_a_frags(fa[(ks + 1) & 1], abase, ks + 1, lane);
                load_b_frags(fb[(ks + 1) & 1], bbase, ks + 1, lane, w);
            }
            mma_tile(acc, fa[ks & 1], fb[ks & 1]);
        }
    }

    // ---- epilogue: scale by 1/z1, store ----
    #pragma unroll
    for (int mt = 0; mt < 4; mt++)
    #pragma unroll
    for (int h = 0; h < 2; h++) {
        const int row = mt * 16 + g + 8 * h;
        const float scl = s_iz[row];
        #pragma unroll
        for (int nt = 0; nt < 4; nt++) {
            const int c = w * 32 + nt * 8 + tg * 2;
            const float2 o = make_float2(acc[mt][nt][2 * h + 0] * scl,
                                         acc[mt][nt][2 * h + 1] * scl);
            *(float2*)(out_read + (t0 + row) * CDIM + c) = o;
        }
    }

    __syncthreads();
    if (tid == 0) {
        atomicAdd(out_scalars + 0, s_acc[0] * (1.0f / 32768.0f));
        atomicAdd(out_scalars + 1, s_acc[1] * (1.0f / (32768.0f * 512.0f)));
        atomicAdd(out_scalars + 2, s_acc[2] * (1.0f / 12800.0f));
    }
}

} // namespace

extern "C" void kernel_launch(void* const* d_in, const int* in_sizes, int n_in,
                              void* d_out, int out_size) {
    const float* key    = (const float*)d_in[0];
    const float* query  = (const float*)d_in[1];
    const float* keys   = (const float*)d_in[2];
    const float* values = (const float*)d_in[3];
    float* out = (float*)d_out;

    const size_t read_elems = (size_t)in_sizes[0];
    const size_t keys_elems = (size_t)in_sizes[2];
    const long long T = (long long)(read_elems / CDIM);

    float* out_scalars = out + read_elems;
    float* out_keys    = out + read_elems + 3;
    float* out_values  = out_keys + keys_elems;

    // single wide prep kernel: bf16 conversions + passthrough copies + zeroing
    prep_kernel<<<256, 256, 0, 0>>>(keys, values, out_keys, out_values, out_scalars);

    static bool attr_set = false;
    if (!attr_set) {
        cudaFuncSetAttribute(memory_module_kernel,
                             cudaFuncAttributeMaxDynamicSharedMemorySize, SMEM_BYTES);
        attr_set = true;
    }

    const int grid = (int)(T / ROWS);   // 512
    memory_module_kernel<<<grid, NT, SMEM_BYTES, 0>>>(key, query, values,
                                                      out, out_scalars);
}